// round 2
// baseline (speedup 1.0000x reference)
#include <cuda_runtime.h>
#include <cstdint>
#include <math.h>

// Problem constants
#define BB   2
#define SS   2048
#define DD   1024
#define HH   16
#define DHH  64
#define MTOT (BB * SS)   // 4096

// Scratch (allocation-free rule: __device__ globals)
__device__ float g_Q[(size_t)MTOT * DD];
__device__ float g_K[(size_t)MTOT * DD];
__device__ float g_V[(size_t)MTOT * DD];
__device__ float g_C[(size_t)MTOT * DD];

// ---------------------------------------------------------------------------
// GEMM: out[r, c] = (sum_k A[r,k] * W[c,k] + bias[c]) * alpha
// A: [MTOT, DD] row-major, W: [DD, DD] row-major (used transposed -> NT GEMM,
// both operands K-contiguous). Tile 64x64, BK=16, 256 threads, 4x4 microtile.
// ---------------------------------------------------------------------------
__global__ __launch_bounds__(256) void gemm_nt_kernel(
    const float* __restrict__ A, const float* __restrict__ W,
    const float* __restrict__ bias, float* __restrict__ out, float alpha)
{
    __shared__ float As[64][17];
    __shared__ float Ws[64][17];

    const int tid  = threadIdx.x;
    const int tx   = tid & 15;        // 0..15 (cols)
    const int ty   = tid >> 4;        // 0..15 (rows)
    const int row0 = blockIdx.y * 64;
    const int col0 = blockIdx.x * 64;

    const int lr = tid >> 2;          // 0..63 tile row for loading
    const int lc = (tid & 3) * 4;     // float4 slot

    float c[4][4];
#pragma unroll
    for (int i = 0; i < 4; i++)
#pragma unroll
        for (int j = 0; j < 4; j++) c[i][j] = 0.f;

    for (int k0 = 0; k0 < DD; k0 += 16) {
        float4 a4 = *(const float4*)(A + (size_t)(row0 + lr) * DD + k0 + lc);
        float4 w4 = *(const float4*)(W + (size_t)(col0 + lr) * DD + k0 + lc);
        As[lr][lc + 0] = a4.x; As[lr][lc + 1] = a4.y;
        As[lr][lc + 2] = a4.z; As[lr][lc + 3] = a4.w;
        Ws[lr][lc + 0] = w4.x; Ws[lr][lc + 1] = w4.y;
        Ws[lr][lc + 2] = w4.z; Ws[lr][lc + 3] = w4.w;
        __syncthreads();

#pragma unroll
        for (int k = 0; k < 16; k++) {
            float a[4], bw[4];
#pragma unroll
            for (int i = 0; i < 4; i++) a[i]  = As[ty * 4 + i][k];
#pragma unroll
            for (int j = 0; j < 4; j++) bw[j] = Ws[tx * 4 + j][k];
#pragma unroll
            for (int i = 0; i < 4; i++)
#pragma unroll
                for (int j = 0; j < 4; j++)
                    c[i][j] = fmaf(a[i], bw[j], c[i][j]);
        }
        __syncthreads();
    }

#pragma unroll
    for (int i = 0; i < 4; i++) {
        const int r = row0 + ty * 4 + i;
#pragma unroll
        for (int j = 0; j < 4; j++) {
            const int cc = col0 + tx * 4 + j;
            out[(size_t)r * DD + cc] = (c[i][j] + bias[cc]) * alpha;
        }
    }
}

// ---------------------------------------------------------------------------
// Flash-style attention. Q/K/V in [B*S, D] layout (head h at col offset h*64).
// One block = 128 query rows of one (b,h); one thread = one query row.
// q[64], o[64], s[16] fully register-resident (all indices statically
// unrolled). K/V staged in 16x64 smem tiles; reads are warp-broadcast.
// Online softmax; mask int != 0 -> score = -1e18 (matches jnp.where).
// MASK IS int32 (jax bool serialized through the harness's int32 dtype).
// ---------------------------------------------------------------------------
__global__ __launch_bounds__(128) void attn_kernel(
    const float* __restrict__ Q, const float* __restrict__ K,
    const float* __restrict__ V, const int* __restrict__ mask,
    float* __restrict__ ctx)
{
    __shared__ float Ks[16][64];
    __shared__ float Vs[16][64];

    const int t  = threadIdx.x;
    const int bh = blockIdx.y;
    const int b  = bh >> 4;       // H = 16
    const int h  = bh & 15;
    const int sq = blockIdx.x * 128 + t;

    const float* qptr = Q + ((size_t)(b * SS + sq)) * DD + h * DHH;
    float q[64], o[64];
#pragma unroll
    for (int d = 0; d < 64; d += 4) {
        float4 v4 = *(const float4*)(qptr + d);
        q[d] = v4.x; q[d + 1] = v4.y; q[d + 2] = v4.z; q[d + 3] = v4.w;
    }
#pragma unroll
    for (int d = 0; d < 64; d++) o[d] = 0.f;

    float m = -INFINITY, l = 0.f;

    const int* mrow = mask + ((size_t)b * SS + sq) * SS;
    const int tc = t & 63;
    const int tr = t >> 6;                       // 0 or 1
    const size_t kvbase = (size_t)(b * SS) * DD + h * DHH;

    for (int kb = 0; kb < SS; kb += 16) {
        __syncthreads();
#pragma unroll
        for (int i = 0; i < 8; i++) {
            const int r = tr + i * 2;            // 0..15
            const size_t g = kvbase + (size_t)(kb + r) * DD + tc;
            Ks[r][tc] = K[g];
            Vs[r][tc] = V[g];
        }
        __syncthreads();

        // 16 mask int32 values for this (row, key-tile): 4 x int4
        int mi[16];
#pragma unroll
        for (int w = 0; w < 4; w++) {
            int4 m4 = *(const int4*)(mrow + kb + w * 4);
            mi[w * 4 + 0] = m4.x; mi[w * 4 + 1] = m4.y;
            mi[w * 4 + 2] = m4.z; mi[w * 4 + 3] = m4.w;
        }

        // scores: s[j] = q . K_j
        float s[16];
#pragma unroll
        for (int j = 0; j < 16; j++) s[j] = 0.f;
#pragma unroll
        for (int d = 0; d < 64; d += 4) {
            const float qx = q[d], qy = q[d + 1], qz = q[d + 2], qw = q[d + 3];
#pragma unroll
            for (int j = 0; j < 16; j++) {
                float4 kv = *(const float4*)(&Ks[j][d]);
                s[j] = fmaf(qx, kv.x, fmaf(qy, kv.y,
                       fmaf(qz, kv.z, fmaf(qw, kv.w, s[j]))));
            }
        }

        // mask + tile max
        float tmax = -INFINITY;
#pragma unroll
        for (int j = 0; j < 16; j++) {
            s[j] = mi[j] ? -1e18f : s[j];
            tmax = fmaxf(tmax, s[j]);
        }

        // online softmax update
        const float newm = fmaxf(m, tmax);
        const float corr = __expf(m - newm);     // exp(-inf)=0 on first tile
        m = newm;
        l *= corr;
#pragma unroll
        for (int d = 0; d < 64; d++) o[d] *= corr;

#pragma unroll
        for (int j = 0; j < 16; j++) {
            const float p = __expf(s[j] - m);
            l += p;
#pragma unroll
            for (int d = 0; d < 64; d += 4) {
                float4 vv = *(const float4*)(&Vs[j][d]);
                o[d]     = fmaf(p, vv.x, o[d]);
                o[d + 1] = fmaf(p, vv.y, o[d + 1]);
                o[d + 2] = fmaf(p, vv.z, o[d + 2]);
                o[d + 3] = fmaf(p, vv.w, o[d + 3]);
            }
        }
    }

    const float inv = 1.0f / l;
    float* cptr = ctx + ((size_t)(b * SS + sq)) * DD + h * DHH;
#pragma unroll
    for (int d = 0; d < 64; d += 4) {
        float4 r4 = make_float4(o[d] * inv, o[d + 1] * inv,
                                o[d + 2] * inv, o[d + 3] * inv);
        *(float4*)(cptr + d) = r4;
    }
}

// ---------------------------------------------------------------------------
// Launch: 3 projection GEMMs -> attention -> output GEMM (same stream).
// ---------------------------------------------------------------------------
extern "C" void kernel_launch(void* const* d_in, const int* in_sizes, int n_in,
                              void* d_out, int out_size)
{
    const float* query = (const float*)d_in[0];
    const int*   mask  = (const int*)d_in[1];
    const float* Wq = (const float*)d_in[2];
    const float* bq = (const float*)d_in[3];
    const float* Wk = (const float*)d_in[4];
    const float* bk = (const float*)d_in[5];
    const float* Wv = (const float*)d_in[6];
    const float* bv = (const float*)d_in[7];
    const float* Wo = (const float*)d_in[8];
    const float* bo = (const float*)d_in[9];
    float* out = (float*)d_out;

    float *gQ, *gK, *gV, *gC;
    cudaGetSymbolAddress((void**)&gQ, g_Q);
    cudaGetSymbolAddress((void**)&gK, g_K);
    cudaGetSymbolAddress((void**)&gV, g_V);
    cudaGetSymbolAddress((void**)&gC, g_C);

    dim3 gGrid(DD / 64, MTOT / 64);   // (16, 64)
    dim3 gBlk(256);

    const float qscale = 0.125f;      // 1/sqrt(DH)
    gemm_nt_kernel<<<gGrid, gBlk>>>(query, Wq, bq, gQ, qscale);
    gemm_nt_kernel<<<gGrid, gBlk>>>(query, Wk, bk, gK, 1.0f);
    gemm_nt_kernel<<<gGrid, gBlk>>>(query, Wv, bv, gV, 1.0f);

    dim3 aGrid(SS / 128, BB * HH);    // (16, 32)
    attn_kernel<<<aGrid, 128>>>(gQ, gK, gV, mask, gC);

    gemm_nt_kernel<<<gGrid, gBlk>>>(gC, Wo, bo, out, 1.0f);
}

// round 4
// speedup vs baseline: 1.3630x; 1.3630x over previous
#include <cuda_runtime.h>
#include <cuda_bf16.h>
#include <cstdint>
#include <math.h>

// Problem constants
#define BB   2
#define SS   2048
#define DD   1024
#define HH   16
#define DHH  64
#define MTOT (BB * SS)   // 4096

// ---------------------------------------------------------------------------
// Scratch (__device__ globals; allocation-free rule)
// ---------------------------------------------------------------------------
__device__ float g_Q[(size_t)MTOT * DD];
__device__ float g_K[(size_t)MTOT * DD];
__device__ float g_V[(size_t)MTOT * DD];
__device__ float g_C[(size_t)MTOT * DD];
__device__ __nv_bfloat16 g_xh[(size_t)MTOT * DD];   // activation hi
__device__ __nv_bfloat16 g_xl[(size_t)MTOT * DD];   // activation lo
__device__ __nv_bfloat16 g_wh[(size_t)DD * DD];     // weight hi
__device__ __nv_bfloat16 g_wl[(size_t)DD * DD];     // weight lo

// ---------------------------------------------------------------------------
// PTX helpers: classic (non-'a') tensor path — mma.sync / ldmatrix / cp.async
// ---------------------------------------------------------------------------
__device__ __forceinline__ uint32_t smem_u32(const void* p) {
    uint32_t a;
    asm("{ .reg .u64 t; cvta.to.shared.u64 t, %1; cvt.u32.u64 %0, t; }"
        : "=r"(a) : "l"(p));
    return a;
}

#define CP_ASYNC16(dst, src) \
    asm volatile("cp.async.cg.shared.global [%0], [%1], 16;" :: "r"(dst), "l"(src))
#define CP_COMMIT() asm volatile("cp.async.commit_group;" ::: "memory")
#define CP_WAIT(n)  asm volatile("cp.async.wait_group %0;" :: "n"(n) : "memory")

__device__ __forceinline__ void ldm_x4(uint32_t* r, uint32_t addr) {
    asm volatile("ldmatrix.sync.aligned.m8n8.x4.shared.b16 {%0,%1,%2,%3}, [%4];"
        : "=r"(r[0]), "=r"(r[1]), "=r"(r[2]), "=r"(r[3]) : "r"(addr));
}
__device__ __forceinline__ void ldm_x2(uint32_t* r, uint32_t addr) {
    asm volatile("ldmatrix.sync.aligned.m8n8.x2.shared.b16 {%0,%1}, [%2];"
        : "=r"(r[0]), "=r"(r[1]) : "r"(addr));
}

// D += A*B  (m16n8k16, bf16 in, fp32 accum)
__device__ __forceinline__ void mma16816(float* c, const uint32_t* a,
                                         const uint32_t* b) {
    asm volatile(
        "mma.sync.aligned.m16n8k16.row.col.f32.bf16.bf16.f32 "
        "{%0,%1,%2,%3}, {%4,%5,%6,%7}, {%8,%9}, {%0,%1,%2,%3};"
        : "+f"(c[0]), "+f"(c[1]), "+f"(c[2]), "+f"(c[3])
        : "r"(a[0]), "r"(a[1]), "r"(a[2]), "r"(a[3]), "r"(b[0]), "r"(b[1]));
}

// ---------------------------------------------------------------------------
// Split fp32 -> bf16 hi + bf16 lo
// ---------------------------------------------------------------------------
__global__ __launch_bounds__(256) void split_kernel(
    const float* __restrict__ x, __nv_bfloat16* __restrict__ hi,
    __nv_bfloat16* __restrict__ lo, int n4)
{
    int i = blockIdx.x * blockDim.x + threadIdx.x;
    if (i >= n4) return;
    float4 v = ((const float4*)x)[i];
    __nv_bfloat16 h0 = __float2bfloat16(v.x);
    __nv_bfloat16 h1 = __float2bfloat16(v.y);
    __nv_bfloat16 h2 = __float2bfloat16(v.z);
    __nv_bfloat16 h3 = __float2bfloat16(v.w);
    __nv_bfloat16 l0 = __float2bfloat16(v.x - __bfloat162float(h0));
    __nv_bfloat16 l1 = __float2bfloat16(v.y - __bfloat162float(h1));
    __nv_bfloat16 l2 = __float2bfloat16(v.z - __bfloat162float(h2));
    __nv_bfloat16 l3 = __float2bfloat16(v.w - __bfloat162float(h3));
    __nv_bfloat162* hp = (__nv_bfloat162*)(hi + (size_t)i * 4);
    __nv_bfloat162* lp = (__nv_bfloat162*)(lo + (size_t)i * 4);
    hp[0] = __nv_bfloat162(h0, h1); hp[1] = __nv_bfloat162(h2, h3);
    lp[0] = __nv_bfloat162(l0, l1); lp[1] = __nv_bfloat162(l2, l3);
}

// ---------------------------------------------------------------------------
// HMMA GEMM: out[m,n] = (sum_k A[m,k]*B[n,k] + bias[n]) * alpha, bf16x3.
// CTA 128x128, 256 thr (8 warps, each 64x32). BK=32, cp.async double buffer.
// Smem tiles [128][40] bf16 (80B rows -> conflict-free ldmatrix).
// ---------------------------------------------------------------------------
#define BKG      32
#define ROWH     40                       // padded halves per row
#define TILE_BY  (128 * ROWH * 2)         // 10240 B
#define OFF_AH   0
#define OFF_AL   (1 * TILE_BY)
#define OFF_WH   (2 * TILE_BY)
#define OFF_WL   (3 * TILE_BY)
#define BUF_BY   (4 * TILE_BY)            // 40960 B
#define SMEM_GG  (2 * BUF_BY)             // 81920 B

__global__ __launch_bounds__(256, 1)
void gemm_mma_kernel(const __nv_bfloat16* __restrict__ Ah,
                     const __nv_bfloat16* __restrict__ Al,
                     const __nv_bfloat16* __restrict__ Bh,
                     const __nv_bfloat16* __restrict__ Bl,
                     const float* __restrict__ bias,
                     float* __restrict__ out, float alpha)
{
    extern __shared__ char smem[];
    const uint32_t sb = smem_u32(smem);
    const int tid  = threadIdx.x;
    const int lane = tid & 31;
    const int w    = tid >> 5;
    const int wm   = w & 1;                // m half (64 rows)
    const int wn   = w >> 1;               // n quarter (32 cols)
    const int row0 = blockIdx.y * 128;
    const int col0 = blockIdx.x * 128;

    float c[4][4][4];
#pragma unroll
    for (int i = 0; i < 4; i++)
#pragma unroll
        for (int j = 0; j < 4; j++)
#pragma unroll
            for (int e = 0; e < 4; e++) c[i][j][e] = 0.f;

    // loader indices: thread covers uint4 u = tid and tid+256 of each tile
    const int r0g = tid >> 2, s0 = tid & 3;          // u = tid
    const int r1g = (tid + 256) >> 2, s1 = s0;       // u = tid+256 (seg same)
    const uint32_t sm0 = (uint32_t)(r0g * (ROWH * 2) + s0 * 16);
    const uint32_t sm1 = (uint32_t)(r1g * (ROWH * 2) + s1 * 16);

    // ldmatrix base offsets (within a tile)
    const uint32_t aoff = (uint32_t)((lane & 15) * (ROWH * 2)
                                     + ((lane >> 4) & 1) * 16);
    const uint32_t boff = (uint32_t)((lane & 7) * (ROWH * 2)
                                     + (((lane & 15) >> 3) & 1) * 16);

    // ---- cp.async issue for chunk cidx into buffer (cidx&1)
    auto issue = [&](int cidx) {
        const uint32_t bb = sb + (uint32_t)(cidx & 1) * BUF_BY;
        const int kc = cidx * BKG;
        const __nv_bfloat16* gAh = Ah + (size_t)(row0 + r0g) * DD + kc + s0 * 8;
        const __nv_bfloat16* gAl = Al + (size_t)(row0 + r0g) * DD + kc + s0 * 8;
        const __nv_bfloat16* gBh = Bh + (size_t)(col0 + r0g) * DD + kc + s0 * 8;
        const __nv_bfloat16* gBl = Bl + (size_t)(col0 + r0g) * DD + kc + s0 * 8;
        CP_ASYNC16(bb + OFF_AH + sm0, gAh);
        CP_ASYNC16(bb + OFF_AL + sm0, gAl);
        CP_ASYNC16(bb + OFF_WH + sm0, gBh);
        CP_ASYNC16(bb + OFF_WL + sm0, gBl);
        const __nv_bfloat16* gAh1 = Ah + (size_t)(row0 + r1g) * DD + kc + s1 * 8;
        const __nv_bfloat16* gAl1 = Al + (size_t)(row0 + r1g) * DD + kc + s1 * 8;
        const __nv_bfloat16* gBh1 = Bh + (size_t)(col0 + r1g) * DD + kc + s1 * 8;
        const __nv_bfloat16* gBl1 = Bl + (size_t)(col0 + r1g) * DD + kc + s1 * 8;
        CP_ASYNC16(bb + OFF_AH + sm1, gAh1);
        CP_ASYNC16(bb + OFF_AL + sm1, gAl1);
        CP_ASYNC16(bb + OFF_WH + sm1, gBh1);
        CP_ASYNC16(bb + OFF_WL + sm1, gBl1);
    };

    const int NCH = DD / BKG;   // 32
    issue(0); CP_COMMIT();

    for (int cidx = 0; cidx < NCH; cidx++) {
        if (cidx + 1 < NCH) { issue(cidx + 1); CP_COMMIT(); CP_WAIT(1); }
        else                { CP_WAIT(0); }
        __syncthreads();

        const uint32_t bb = sb + (uint32_t)(cidx & 1) * BUF_BY;
#pragma unroll
        for (int ks = 0; ks < 2; ks++) {
            const uint32_t k0b = (uint32_t)(ks * 16 * 2);
            uint32_t ah[4][4], al[4][4], bh[4][2], bl[4][2];
#pragma unroll
            for (int i = 0; i < 4; i++) {
                const uint32_t ao = (uint32_t)((wm * 64 + i * 16) * (ROWH * 2))
                                  + aoff + k0b;
                ldm_x4(ah[i], bb + OFF_AH + ao);
                ldm_x4(al[i], bb + OFF_AL + ao);
            }
#pragma unroll
            for (int j = 0; j < 4; j++) {
                const uint32_t bo = (uint32_t)((wn * 32 + j * 8) * (ROWH * 2))
                                  + boff + k0b;
                ldm_x2(bh[j], bb + OFF_WH + bo);
                ldm_x2(bl[j], bb + OFF_WL + bo);
            }
#pragma unroll
            for (int i = 0; i < 4; i++)
#pragma unroll
                for (int j = 0; j < 4; j++) {
                    mma16816(c[i][j], ah[i], bh[j]);
                    mma16816(c[i][j], ah[i], bl[j]);
                    mma16816(c[i][j], al[i], bh[j]);
                }
        }
        __syncthreads();
    }

    // ---- epilogue: (acc + bias) * alpha
    const int g  = lane >> 2;
    const int tq = lane & 3;
#pragma unroll
    for (int i = 0; i < 4; i++) {
        const int mrow = row0 + wm * 64 + i * 16 + g;
#pragma unroll
        for (int j = 0; j < 4; j++) {
            const int col = col0 + wn * 32 + j * 8 + tq * 2;
            const float b0 = bias[col], b1 = bias[col + 1];
            float2 v0 = make_float2((c[i][j][0] + b0) * alpha,
                                    (c[i][j][1] + b1) * alpha);
            float2 v1 = make_float2((c[i][j][2] + b0) * alpha,
                                    (c[i][j][3] + b1) * alpha);
            *(float2*)(out + (size_t)mrow * DD + col)       = v0;
            *(float2*)(out + (size_t)(mrow + 8) * DD + col) = v1;
        }
    }
}

// ---------------------------------------------------------------------------
// Flash-style attention (unchanged passing R2 version).
// ---------------------------------------------------------------------------
__global__ __launch_bounds__(128) void attn_kernel(
    const float* __restrict__ Q, const float* __restrict__ K,
    const float* __restrict__ V, const int* __restrict__ mask,
    float* __restrict__ ctx)
{
    __shared__ float Ks[16][64];
    __shared__ float Vs[16][64];

    const int t  = threadIdx.x;
    const int bh = blockIdx.y;
    const int b  = bh >> 4;
    const int h  = bh & 15;
    const int sq = blockIdx.x * 128 + t;

    const float* qptr = Q + ((size_t)(b * SS + sq)) * DD + h * DHH;
    float q[64], o[64];
#pragma unroll
    for (int d = 0; d < 64; d += 4) {
        float4 v4 = *(const float4*)(qptr + d);
        q[d] = v4.x; q[d + 1] = v4.y; q[d + 2] = v4.z; q[d + 3] = v4.w;
    }
#pragma unroll
    for (int d = 0; d < 64; d++) o[d] = 0.f;

    float m = -INFINITY, l = 0.f;

    const int* mrow = mask + ((size_t)b * SS + sq) * SS;
    const int tc = t & 63;
    const int tr = t >> 6;
    const size_t kvbase = (size_t)(b * SS) * DD + h * DHH;

    for (int kb = 0; kb < SS; kb += 16) {
        __syncthreads();
#pragma unroll
        for (int i = 0; i < 8; i++) {
            const int r = tr + i * 2;
            const size_t gidx = kvbase + (size_t)(kb + r) * DD + tc;
            Ks[r][tc] = K[gidx];
            Vs[r][tc] = V[gidx];
        }
        __syncthreads();

        int mi[16];
#pragma unroll
        for (int wq = 0; wq < 4; wq++) {
            int4 m4 = *(const int4*)(mrow + kb + wq * 4);
            mi[wq * 4 + 0] = m4.x; mi[wq * 4 + 1] = m4.y;
            mi[wq * 4 + 2] = m4.z; mi[wq * 4 + 3] = m4.w;
        }

        float s[16];
#pragma unroll
        for (int j = 0; j < 16; j++) s[j] = 0.f;
#pragma unroll
        for (int d = 0; d < 64; d += 4) {
            const float qx = q[d], qy = q[d + 1], qz = q[d + 2], qw = q[d + 3];
#pragma unroll
            for (int j = 0; j < 16; j++) {
                float4 kv = *(const float4*)(&Ks[j][d]);
                s[j] = fmaf(qx, kv.x, fmaf(qy, kv.y,
                       fmaf(qz, kv.z, fmaf(qw, kv.w, s[j]))));
            }
        }

        float tmax = -INFINITY;
#pragma unroll
        for (int j = 0; j < 16; j++) {
            s[j] = mi[j] ? -1e18f : s[j];
            tmax = fmaxf(tmax, s[j]);
        }

        const float newm = fmaxf(m, tmax);
        const float corr = __expf(m - newm);
        m = newm;
        l *= corr;
#pragma unroll
        for (int d = 0; d < 64; d++) o[d] *= corr;

#pragma unroll
        for (int j = 0; j < 16; j++) {
            const float p = __expf(s[j] - m);
            l += p;
#pragma unroll
            for (int d = 0; d < 64; d += 4) {
                float4 vv = *(const float4*)(&Vs[j][d]);
                o[d]     = fmaf(p, vv.x, o[d]);
                o[d + 1] = fmaf(p, vv.y, o[d + 1]);
                o[d + 2] = fmaf(p, vv.z, o[d + 2]);
                o[d + 3] = fmaf(p, vv.w, o[d + 3]);
            }
        }
    }

    const float inv = 1.0f / l;
    float* cptr = ctx + ((size_t)(b * SS + sq)) * DD + h * DHH;
#pragma unroll
    for (int d = 0; d < 64; d += 4) {
        float4 r4 = make_float4(o[d] * inv, o[d + 1] * inv,
                                o[d + 2] * inv, o[d + 3] * inv);
        *(float4*)(cptr + d) = r4;
    }
}

// ---------------------------------------------------------------------------
// Launch
// ---------------------------------------------------------------------------
extern "C" void kernel_launch(void* const* d_in, const int* in_sizes, int n_in,
                              void* d_out, int out_size)
{
    const float* query = (const float*)d_in[0];
    const int*   mask  = (const int*)d_in[1];
    const float* Wq = (const float*)d_in[2];
    const float* bq = (const float*)d_in[3];
    const float* Wk = (const float*)d_in[4];
    const float* bk = (const float*)d_in[5];
    const float* Wv = (const float*)d_in[6];
    const float* bv = (const float*)d_in[7];
    const float* Wo = (const float*)d_in[8];
    const float* bo = (const float*)d_in[9];
    float* out = (float*)d_out;

    float *gQ, *gK, *gV, *gC;
    __nv_bfloat16 *xh, *xl, *wh, *wl;
    cudaGetSymbolAddress((void**)&gQ, g_Q);
    cudaGetSymbolAddress((void**)&gK, g_K);
    cudaGetSymbolAddress((void**)&gV, g_V);
    cudaGetSymbolAddress((void**)&gC, g_C);
    cudaGetSymbolAddress((void**)&xh, g_xh);
    cudaGetSymbolAddress((void**)&xl, g_xl);
    cudaGetSymbolAddress((void**)&wh, g_wh);
    cudaGetSymbolAddress((void**)&wl, g_wl);

    cudaFuncSetAttribute(gemm_mma_kernel,
                         cudaFuncAttributeMaxDynamicSharedMemorySize, SMEM_GG);

    const int nX4 = MTOT * DD / 4;
    const int nW4 = DD * DD / 4;
    dim3 sxG((nX4 + 255) / 256), swG((nW4 + 255) / 256);
    dim3 mmG(DD / 128, MTOT / 128);  // (8, 32)

    split_kernel<<<sxG, 256>>>(query, xh, xl, nX4);

    split_kernel<<<swG, 256>>>(Wq, wh, wl, nW4);
    gemm_mma_kernel<<<mmG, 256, SMEM_GG>>>(xh, xl, wh, wl, bq, gQ, 0.125f);

    split_kernel<<<swG, 256>>>(Wk, wh, wl, nW4);
    gemm_mma_kernel<<<mmG, 256, SMEM_GG>>>(xh, xl, wh, wl, bk, gK, 1.0f);

    split_kernel<<<swG, 256>>>(Wv, wh, wl, nW4);
    gemm_mma_kernel<<<mmG, 256, SMEM_GG>>>(xh, xl, wh, wl, bv, gV, 1.0f);

    dim3 aGrid(SS / 128, BB * HH);
    attn_kernel<<<aGrid, 128>>>(gQ, gK, gV, mask, gC);

    split_kernel<<<sxG, 256>>>(gC, xh, xl, nX4);
    split_kernel<<<swG, 256>>>(Wo, wh, wl, nW4);
    gemm_mma_kernel<<<mmG, 256, SMEM_GG>>>(xh, xl, wh, wl, bo, out, 1.0f);
}

// round 5
// speedup vs baseline: 3.3072x; 2.4264x over previous
#include <cuda_runtime.h>
#include <cuda_bf16.h>
#include <cstdint>
#include <math.h>

// Problem constants
#define BB   2
#define SS   2048
#define DD   1024
#define HH   16
#define DHH  64
#define MTOT (BB * SS)   // 4096

// ---------------------------------------------------------------------------
// Scratch (__device__ globals; allocation-free rule)
// ---------------------------------------------------------------------------
__device__ __nv_bfloat16 g_xh[(size_t)MTOT * DD];       // query split hi
__device__ __nv_bfloat16 g_xl[(size_t)MTOT * DD];       // query split lo
__device__ __nv_bfloat16 g_wh[3 * (size_t)DD * DD];     // weight hi (x3)
__device__ __nv_bfloat16 g_wl[3 * (size_t)DD * DD];     // weight lo (x3)
__device__ __nv_bfloat16 g_qh[(size_t)MTOT * DD];       // [B,H,S,64]
__device__ __nv_bfloat16 g_ql[(size_t)MTOT * DD];
__device__ __nv_bfloat16 g_kh[(size_t)MTOT * DD];
__device__ __nv_bfloat16 g_kl[(size_t)MTOT * DD];
__device__ __nv_bfloat16 g_vh[(size_t)MTOT * DD];
__device__ __nv_bfloat16 g_vl[(size_t)MTOT * DD];
__device__ __nv_bfloat16 g_ch[(size_t)MTOT * DD];       // ctx hi [MTOT][DD]
__device__ __nv_bfloat16 g_cl[(size_t)MTOT * DD];
__device__ __nv_bfloat16 g_bias[(size_t)BB * SS * SS];  // additive mask bias

// ---------------------------------------------------------------------------
// PTX helpers (classic tensor path: mma.sync / ldmatrix / cp.async)
// ---------------------------------------------------------------------------
__device__ __forceinline__ uint32_t smem_u32(const void* p) {
    uint32_t a;
    asm("{ .reg .u64 t; cvta.to.shared.u64 t, %1; cvt.u32.u64 %0, t; }"
        : "=r"(a) : "l"(p));
    return a;
}
#define CP_ASYNC16(dst, src) \
    asm volatile("cp.async.cg.shared.global [%0], [%1], 16;" :: "r"(dst), "l"(src))
#define CP_COMMIT() asm volatile("cp.async.commit_group;" ::: "memory")
#define CP_WAIT(n)  asm volatile("cp.async.wait_group %0;" :: "n"(n) : "memory")

__device__ __forceinline__ void ldm_x4(uint32_t* r, uint32_t addr) {
    asm volatile("ldmatrix.sync.aligned.m8n8.x4.shared.b16 {%0,%1,%2,%3}, [%4];"
        : "=r"(r[0]), "=r"(r[1]), "=r"(r[2]), "=r"(r[3]) : "r"(addr));
}
__device__ __forceinline__ void ldm_x2(uint32_t* r, uint32_t addr) {
    asm volatile("ldmatrix.sync.aligned.m8n8.x2.shared.b16 {%0,%1}, [%2];"
        : "=r"(r[0]), "=r"(r[1]) : "r"(addr));
}
__device__ __forceinline__ void ldm_x2t(uint32_t* r, uint32_t addr) {
    asm volatile("ldmatrix.sync.aligned.m8n8.x2.trans.shared.b16 {%0,%1}, [%2];"
        : "=r"(r[0]), "=r"(r[1]) : "r"(addr));
}
__device__ __forceinline__ void mma16816(float* c, const uint32_t* a,
                                         const uint32_t* b) {
    asm volatile(
        "mma.sync.aligned.m16n8k16.row.col.f32.bf16.bf16.f32 "
        "{%0,%1,%2,%3}, {%4,%5,%6,%7}, {%8,%9}, {%0,%1,%2,%3};"
        : "+f"(c[0]), "+f"(c[1]), "+f"(c[2]), "+f"(c[3])
        : "r"(a[0]), "r"(a[1]), "r"(a[2]), "r"(a[3]), "r"(b[0]), "r"(b[1]));
}
__device__ __forceinline__ uint32_t bc32(__nv_bfloat162 v) {
    return *reinterpret_cast<uint32_t*>(&v);
}

// ---------------------------------------------------------------------------
// Split fp32 -> bf16 hi + lo
// ---------------------------------------------------------------------------
__global__ __launch_bounds__(256) void split_kernel(
    const float* __restrict__ x, __nv_bfloat16* __restrict__ hi,
    __nv_bfloat16* __restrict__ lo, int n4)
{
    int i = blockIdx.x * blockDim.x + threadIdx.x;
    if (i >= n4) return;
    float4 v = ((const float4*)x)[i];
    __nv_bfloat16 h0 = __float2bfloat16(v.x), h1 = __float2bfloat16(v.y);
    __nv_bfloat16 h2 = __float2bfloat16(v.z), h3 = __float2bfloat16(v.w);
    __nv_bfloat16 l0 = __float2bfloat16(v.x - __bfloat162float(h0));
    __nv_bfloat16 l1 = __float2bfloat16(v.y - __bfloat162float(h1));
    __nv_bfloat16 l2 = __float2bfloat16(v.z - __bfloat162float(h2));
    __nv_bfloat16 l3 = __float2bfloat16(v.w - __bfloat162float(h3));
    __nv_bfloat162* hp = (__nv_bfloat162*)(hi + (size_t)i * 4);
    __nv_bfloat162* lp = (__nv_bfloat162*)(lo + (size_t)i * 4);
    hp[0] = __nv_bfloat162(h0, h1); hp[1] = __nv_bfloat162(h2, h3);
    lp[0] = __nv_bfloat162(l0, l1); lp[1] = __nv_bfloat162(l2, l3);
}

// int32 mask -> additive bf16 bias (0 or -1e18)
__global__ __launch_bounds__(256) void maskbias_kernel(
    const int* __restrict__ m, __nv_bfloat16* __restrict__ bias, int n4)
{
    int i = blockIdx.x * blockDim.x + threadIdx.x;
    if (i >= n4) return;
    int4 v = ((const int4*)m)[i];
    const __nv_bfloat16 z = __float2bfloat16(0.f);
    const __nv_bfloat16 n = __float2bfloat16(-1e18f);
    __nv_bfloat162* bp = (__nv_bfloat162*)(bias + (size_t)i * 4);
    bp[0] = __nv_bfloat162(v.x ? n : z, v.y ? n : z);
    bp[1] = __nv_bfloat162(v.z ? n : z, v.w ? n : z);
}

// ---------------------------------------------------------------------------
// Shared GEMM mainloop pieces (bf16x3, CTA 128x128, BK=32, double buffer)
// ---------------------------------------------------------------------------
#define BKG      32
#define ROWH     40                       // padded halves per row (80B)
#define TILE_BY  (128 * ROWH * 2)         // 10240 B
#define OFF_AH   0
#define OFF_AL   (1 * TILE_BY)
#define OFF_WH   (2 * TILE_BY)
#define OFF_WL   (3 * TILE_BY)
#define BUF_BY   (4 * TILE_BY)
#define SMEM_GG  (2 * BUF_BY)             // 81920 B

struct GemmAcc { float c[4][4][4]; };

__device__ __forceinline__ void gemm_mainloop(
    const __nv_bfloat16* Ah, const __nv_bfloat16* Al,
    const __nv_bfloat16* Bh, const __nv_bfloat16* Bl,
    int row0, int col0, uint32_t sb, GemmAcc& acc)
{
    const int tid  = threadIdx.x;
    const int lane = tid & 31;
    const int w    = tid >> 5;
    const int wm   = w & 1;
    const int wn   = w >> 1;

#pragma unroll
    for (int i = 0; i < 4; i++)
#pragma unroll
        for (int j = 0; j < 4; j++)
#pragma unroll
            for (int e = 0; e < 4; e++) acc.c[i][j][e] = 0.f;

    const int r0g = tid >> 2, s0 = tid & 3;
    const int r1g = (tid + 256) >> 2;
    const uint32_t sm0 = (uint32_t)(r0g * (ROWH * 2) + s0 * 16);
    const uint32_t sm1 = (uint32_t)(r1g * (ROWH * 2) + s0 * 16);

    const uint32_t aoff = (uint32_t)((lane & 15) * (ROWH * 2)
                                     + ((lane >> 4) & 1) * 16);
    const uint32_t boff = (uint32_t)((lane & 7) * (ROWH * 2)
                                     + ((lane >> 3) & 1) * 16);

    auto issue = [&](int cidx) {
        const uint32_t bb = sb + (uint32_t)(cidx & 1) * BUF_BY;
        const int kc = cidx * BKG;
        CP_ASYNC16(bb + OFF_AH + sm0, Ah + (size_t)(row0 + r0g) * DD + kc + s0 * 8);
        CP_ASYNC16(bb + OFF_AL + sm0, Al + (size_t)(row0 + r0g) * DD + kc + s0 * 8);
        CP_ASYNC16(bb + OFF_WH + sm0, Bh + (size_t)(col0 + r0g) * DD + kc + s0 * 8);
        CP_ASYNC16(bb + OFF_WL + sm0, Bl + (size_t)(col0 + r0g) * DD + kc + s0 * 8);
        CP_ASYNC16(bb + OFF_AH + sm1, Ah + (size_t)(row0 + r1g) * DD + kc + s0 * 8);
        CP_ASYNC16(bb + OFF_AL + sm1, Al + (size_t)(row0 + r1g) * DD + kc + s0 * 8);
        CP_ASYNC16(bb + OFF_WH + sm1, Bh + (size_t)(col0 + r1g) * DD + kc + s0 * 8);
        CP_ASYNC16(bb + OFF_WL + sm1, Bl + (size_t)(col0 + r1g) * DD + kc + s0 * 8);
    };

    const int NCH = DD / BKG;
    issue(0); CP_COMMIT();

    for (int cidx = 0; cidx < NCH; cidx++) {
        if (cidx + 1 < NCH) { issue(cidx + 1); CP_COMMIT(); CP_WAIT(1); }
        else                { CP_WAIT(0); }
        __syncthreads();

        const uint32_t bb = sb + (uint32_t)(cidx & 1) * BUF_BY;
#pragma unroll
        for (int ks = 0; ks < 2; ks++) {
            const uint32_t k0b = (uint32_t)(ks * 32);
            uint32_t ah[4][4], al[4][4], bh[4][2], bl[4][2];
#pragma unroll
            for (int i = 0; i < 4; i++) {
                const uint32_t ao = (uint32_t)((wm * 64 + i * 16) * (ROWH * 2))
                                  + aoff + k0b;
                ldm_x4(ah[i], bb + OFF_AH + ao);
                ldm_x4(al[i], bb + OFF_AL + ao);
            }
#pragma unroll
            for (int j = 0; j < 4; j++) {
                const uint32_t bo = (uint32_t)((wn * 32 + j * 8) * (ROWH * 2))
                                  + boff + k0b;
                ldm_x2(bh[j], bb + OFF_WH + bo);
                ldm_x2(bl[j], bb + OFF_WL + bo);
            }
#pragma unroll
            for (int i = 0; i < 4; i++)
#pragma unroll
                for (int j = 0; j < 4; j++) {
                    mma16816(acc.c[i][j], ah[i], bh[j]);
                    mma16816(acc.c[i][j], ah[i], bl[j]);
                    mma16816(acc.c[i][j], al[i], bh[j]);
                }
        }
        __syncthreads();
    }
}

// ---- final GEMM: fp32 out = (acc + bias) (Wo path)
__global__ __launch_bounds__(256, 1)
void gemm_out_kernel(const __nv_bfloat16* __restrict__ Ah,
                     const __nv_bfloat16* __restrict__ Al,
                     const __nv_bfloat16* __restrict__ Bh,
                     const __nv_bfloat16* __restrict__ Bl,
                     const float* __restrict__ bias,
                     float* __restrict__ out)
{
    extern __shared__ char smem[];
    const uint32_t sb = smem_u32(smem);
    const int lane = threadIdx.x & 31;
    const int w    = threadIdx.x >> 5;
    const int wm = w & 1, wn = w >> 1;
    const int row0 = blockIdx.y * 128, col0 = blockIdx.x * 128;

    GemmAcc acc;
    gemm_mainloop(Ah, Al, Bh, Bl, row0, col0, sb, acc);

    const int g = lane >> 2, tq = lane & 3;
#pragma unroll
    for (int i = 0; i < 4; i++) {
        const int mrow = row0 + wm * 64 + i * 16 + g;
#pragma unroll
        for (int j = 0; j < 4; j++) {
            const int col = col0 + wn * 32 + j * 8 + tq * 2;
            const float b0 = bias[col], b1 = bias[col + 1];
            *(float2*)(out + (size_t)mrow * DD + col) =
                make_float2(acc.c[i][j][0] + b0, acc.c[i][j][1] + b1);
            *(float2*)(out + (size_t)(mrow + 8) * DD + col) =
                make_float2(acc.c[i][j][2] + b0, acc.c[i][j][3] + b1);
        }
    }
}

// ---- QKV GEMM: z selects weight/bias/alpha; epilogue splits to hi/lo [B,H,S,64]
__global__ __launch_bounds__(256, 1)
void gemm_qkv_kernel(const __nv_bfloat16* __restrict__ Ah,
                     const __nv_bfloat16* __restrict__ Al,
                     const __nv_bfloat16* __restrict__ WH,
                     const __nv_bfloat16* __restrict__ WL,
                     const float* __restrict__ bq, const float* __restrict__ bk,
                     const float* __restrict__ bv,
                     __nv_bfloat16* __restrict__ qh, __nv_bfloat16* __restrict__ ql,
                     __nv_bfloat16* __restrict__ kh, __nv_bfloat16* __restrict__ kl,
                     __nv_bfloat16* __restrict__ vh, __nv_bfloat16* __restrict__ vl)
{
    extern __shared__ char smem[];
    const uint32_t sb = smem_u32(smem);
    const int z = blockIdx.z;
    const __nv_bfloat16* Bh = WH + (size_t)z * DD * DD;
    const __nv_bfloat16* Bl = WL + (size_t)z * DD * DD;
    const float* bias = (z == 0) ? bq : (z == 1) ? bk : bv;
    __nv_bfloat16* Oh = (z == 0) ? qh : (z == 1) ? kh : vh;
    __nv_bfloat16* Ol = (z == 0) ? ql : (z == 1) ? kl : vl;
    const float alpha = (z == 0) ? 0.125f : 1.0f;

    const int lane = threadIdx.x & 31;
    const int w    = threadIdx.x >> 5;
    const int wm = w & 1, wn = w >> 1;
    const int row0 = blockIdx.y * 128, col0 = blockIdx.x * 128;

    GemmAcc acc;
    gemm_mainloop(Ah, Al, Bh, Bl, row0, col0, sb, acc);

    const int g = lane >> 2, tq = lane & 3;
#pragma unroll
    for (int i = 0; i < 4; i++) {
        const int m0r = row0 + wm * 64 + i * 16 + g;
#pragma unroll
        for (int j = 0; j < 4; j++) {
            const int col = col0 + wn * 32 + j * 8 + tq * 2;
            const float b0 = bias[col], b1 = bias[col + 1];
            const int h = col >> 6, d = col & 63;
#pragma unroll
            for (int half = 0; half < 2; half++) {
                const int m = m0r + half * 8;
                const int b = m >> 11, s = m & 2047;
                const float v0 = (acc.c[i][j][half * 2 + 0] + b0) * alpha;
                const float v1 = (acc.c[i][j][half * 2 + 1] + b1) * alpha;
                __nv_bfloat162 hp = __float22bfloat162_rn(make_float2(v0, v1));
                float2 hf = __bfloat1622float2(hp);
                __nv_bfloat162 lp = __float22bfloat162_rn(
                    make_float2(v0 - hf.x, v1 - hf.y));
                const size_t o = (((size_t)(b * HH + h) * SS + s) << 6) + d;
                *(__nv_bfloat162*)(Oh + o) = hp;
                *(__nv_bfloat162*)(Ol + o) = lp;
            }
        }
    }
}

// ---------------------------------------------------------------------------
// Flash attention via mma.sync, bf16x3 QK and PV.
// CTA: 128 q-rows x one (b,h). 8 warps x m16. K/V 64-key tiles, double buffer.
// ---------------------------------------------------------------------------
#define DPADB   144                     // bytes per smem row (64 bf16 + pad)
#define QTILE_B (128 * DPADB)           // 18432
#define KVT_B   (64 * DPADB)            // 9216
#define AOFF_QH 0
#define AOFF_QL QTILE_B
#define AOFF_ST (2 * QTILE_B)
#define STAGE_B (4 * KVT_B)             // Kh,Kl,Vh,Vl
#define AOFF_KH 0
#define AOFF_KL (1 * KVT_B)
#define AOFF_VH (2 * KVT_B)
#define AOFF_VL (3 * KVT_B)
#define SMEM_ATT (2 * QTILE_B + 2 * STAGE_B)   // 110592

__global__ __launch_bounds__(256, 1)
void attn_mma_kernel(const __nv_bfloat16* __restrict__ Qh,
                     const __nv_bfloat16* __restrict__ Ql,
                     const __nv_bfloat16* __restrict__ Kh,
                     const __nv_bfloat16* __restrict__ Kl,
                     const __nv_bfloat16* __restrict__ Vh,
                     const __nv_bfloat16* __restrict__ Vl,
                     const __nv_bfloat16* __restrict__ bias,
                     __nv_bfloat16* __restrict__ Ch,
                     __nv_bfloat16* __restrict__ Cl)
{
    extern __shared__ char smem[];
    const uint32_t sb = smem_u32(smem);
    const int tid = threadIdx.x, lane = tid & 31, w = tid >> 5;
    const int bh = blockIdx.y, b = bh >> 4, h = bh & 15;
    const int q0 = blockIdx.x * 128;
    const size_t hoff = (size_t)bh * SS * 64;

    auto issue_kv = [&](int kt) {
        const uint32_t st = sb + AOFF_ST + (uint32_t)(kt & 1) * STAGE_B;
#pragma unroll
        for (int u = tid; u < 512; u += 256) {
            const int r = u >> 3, sg = u & 7;
            const uint32_t so = (uint32_t)(r * DPADB + sg * 16);
            const size_t go = hoff + (size_t)(kt * 64 + r) * 64 + sg * 8;
            CP_ASYNC16(st + AOFF_KH + so, Kh + go);
            CP_ASYNC16(st + AOFF_KL + so, Kl + go);
            CP_ASYNC16(st + AOFF_VH + so, Vh + go);
            CP_ASYNC16(st + AOFF_VL + so, Vl + go);
        }
    };

    // Q tiles + stage 0 (group), stage 1 (group)
    for (int u = tid; u < 1024; u += 256) {
        const int r = u >> 3, sg = u & 7;
        const uint32_t so = (uint32_t)(r * DPADB + sg * 16);
        const size_t go = hoff + (size_t)(q0 + r) * 64 + sg * 8;
        CP_ASYNC16(sb + AOFF_QH + so, Qh + go);
        CP_ASYNC16(sb + AOFF_QL + so, Ql + go);
    }
    issue_kv(0); CP_COMMIT();
    issue_kv(1); CP_COMMIT();
    CP_WAIT(1); __syncthreads();

    // Q fragments (persistent)
    uint32_t qfh[4][4], qfl[4][4];
    const uint32_t aoff = (uint32_t)((w * 16 + (lane & 15)) * DPADB
                                     + ((lane >> 4) & 1) * 16);
#pragma unroll
    for (int c = 0; c < 4; c++) {
        ldm_x4(qfh[c], sb + AOFF_QH + aoff + c * 32);
        ldm_x4(qfl[c], sb + AOFF_QL + aoff + c * 32);
    }

    float O[8][4];
#pragma unroll
    for (int j = 0; j < 8; j++)
#pragma unroll
        for (int e = 0; e < 4; e++) O[j][e] = 0.f;
    float m0 = -INFINITY, m1 = -INFINITY, l0 = 0.f, l1 = 0.f;

    const int qrow = q0 + w * 16 + (lane >> 2);
    const __nv_bfloat16* bp0 = bias + ((size_t)b * SS + qrow) * SS;
    const __nv_bfloat16* bp1 = bp0 + (size_t)8 * SS;
    const int tq2 = (lane & 3) * 2;

    const uint32_t koff_b = (uint32_t)((lane & 7) * DPADB + ((lane >> 3) & 1) * 16);
    const uint32_t voff_b = (uint32_t)((lane & 15) * DPADB);

    for (int kt = 0; kt < 32; kt++) {
        const uint32_t st = sb + AOFF_ST + (uint32_t)(kt & 1) * STAGE_B;

        // ---- scores S = Q.K^T (bf16x3)
        float S[8][4];
#pragma unroll
        for (int j = 0; j < 8; j++)
#pragma unroll
            for (int e = 0; e < 4; e++) S[j][e] = 0.f;
#pragma unroll
        for (int c = 0; c < 4; c++)
#pragma unroll
            for (int j = 0; j < 8; j++) {
                uint32_t kh2[2], kl2[2];
                const uint32_t ko = (uint32_t)(j * 8 * DPADB) + koff_b + c * 32;
                ldm_x2(kh2, st + AOFF_KH + ko);
                ldm_x2(kl2, st + AOFF_KL + ko);
                mma16816(S[j], qfh[c], kh2);
                mma16816(S[j], qfh[c], kl2);
                mma16816(S[j], qfl[c], kh2);
            }

        // ---- bias + row max
        const int kt64 = kt * 64;
        float mx0 = -INFINITY, mx1 = -INFINITY;
#pragma unroll
        for (int j = 0; j < 8; j++) {
            const int kcol = kt64 + j * 8 + tq2;
            float2 b0 = __bfloat1622float2(*(const __nv_bfloat162*)(bp0 + kcol));
            float2 b1 = __bfloat1622float2(*(const __nv_bfloat162*)(bp1 + kcol));
            S[j][0] += b0.x; S[j][1] += b0.y;
            S[j][2] += b1.x; S[j][3] += b1.y;
            mx0 = fmaxf(mx0, fmaxf(S[j][0], S[j][1]));
            mx1 = fmaxf(mx1, fmaxf(S[j][2], S[j][3]));
        }
        mx0 = fmaxf(mx0, __shfl_xor_sync(0xFFFFFFFFu, mx0, 1));
        mx0 = fmaxf(mx0, __shfl_xor_sync(0xFFFFFFFFu, mx0, 2));
        mx1 = fmaxf(mx1, __shfl_xor_sync(0xFFFFFFFFu, mx1, 1));
        mx1 = fmaxf(mx1, __shfl_xor_sync(0xFFFFFFFFu, mx1, 2));

        const float mn0 = fmaxf(m0, mx0), mn1 = fmaxf(m1, mx1);
        const float cr0 = __expf(m0 - mn0), cr1 = __expf(m1 - mn1);
        m0 = mn0; m1 = mn1;
        l0 *= cr0; l1 *= cr1;
#pragma unroll
        for (int j = 0; j < 8; j++) {
            O[j][0] *= cr0; O[j][1] *= cr0;
            O[j][2] *= cr1; O[j][3] *= cr1;
        }

        // ---- exp + split P to bf16 hi/lo fragments
        uint32_t PH[8][2], PL[8][2];
#pragma unroll
        for (int j = 0; j < 8; j++) {
            const float p0 = __expf(S[j][0] - m0), p1 = __expf(S[j][1] - m0);
            const float p2 = __expf(S[j][2] - m1), p3 = __expf(S[j][3] - m1);
            l0 += p0 + p1; l1 += p2 + p3;
            __nv_bfloat162 h01 = __float22bfloat162_rn(make_float2(p0, p1));
            float2 hf01 = __bfloat1622float2(h01);
            __nv_bfloat162 l01 = __float22bfloat162_rn(
                make_float2(p0 - hf01.x, p1 - hf01.y));
            __nv_bfloat162 h23 = __float22bfloat162_rn(make_float2(p2, p3));
            float2 hf23 = __bfloat1622float2(h23);
            __nv_bfloat162 l23 = __float22bfloat162_rn(
                make_float2(p2 - hf23.x, p3 - hf23.y));
            PH[j][0] = bc32(h01); PH[j][1] = bc32(h23);
            PL[j][0] = bc32(l01); PL[j][1] = bc32(l23);
        }

        // ---- O += P.V (bf16x3), V via ldmatrix.trans
#pragma unroll
        for (int t = 0; t < 4; t++) {
            uint32_t ah[4] = { PH[2*t][0], PH[2*t][1], PH[2*t+1][0], PH[2*t+1][1] };
            uint32_t al[4] = { PL[2*t][0], PL[2*t][1], PL[2*t+1][0], PL[2*t+1][1] };
#pragma unroll
            for (int j = 0; j < 8; j++) {
                uint32_t vh2[2], vl2[2];
                const uint32_t vo = (uint32_t)(t * 16 * DPADB) + voff_b + j * 16;
                ldm_x2t(vh2, st + AOFF_VH + vo);
                ldm_x2t(vl2, st + AOFF_VL + vo);
                mma16816(O[j], ah, vh2);
                mma16816(O[j], ah, vl2);
                mma16816(O[j], al, vh2);
            }
        }

        __syncthreads();                       // done reading stage (kt&1)
        if (kt + 1 < 32) {
            if (kt + 2 < 32) { issue_kv(kt + 2); CP_COMMIT(); CP_WAIT(1); }
            else             { CP_WAIT(0); }
            __syncthreads();
        }
    }

    // ---- epilogue
    l0 += __shfl_xor_sync(0xFFFFFFFFu, l0, 1);
    l0 += __shfl_xor_sync(0xFFFFFFFFu, l0, 2);
    l1 += __shfl_xor_sync(0xFFFFFFFFu, l1, 1);
    l1 += __shfl_xor_sync(0xFFFFFFFFu, l1, 2);
    const float i0 = 1.f / l0, i1 = 1.f / l1;

    const size_t r0 = (size_t)(b * SS + qrow);
    const size_t r1 = r0 + 8;
    const int colb = h * 64 + tq2;
#pragma unroll
    for (int j = 0; j < 8; j++) {
        const int col = colb + j * 8;
        const float v0 = O[j][0] * i0, v1 = O[j][1] * i0;
        const float v2 = O[j][2] * i1, v3 = O[j][3] * i1;
        __nv_bfloat162 h01 = __float22bfloat162_rn(make_float2(v0, v1));
        float2 hf01 = __bfloat1622float2(h01);
        __nv_bfloat162 l01 = __float22bfloat162_rn(make_float2(v0 - hf01.x, v1 - hf01.y));
        __nv_bfloat162 h23 = __float22bfloat162_rn(make_float2(v2, v3));
        float2 hf23 = __bfloat1622float2(h23);
        __nv_bfloat162 l23 = __float22bfloat162_rn(make_float2(v2 - hf23.x, v3 - hf23.y));
        *(__nv_bfloat162*)(Ch + r0 * DD + col) = h01;
        *(__nv_bfloat162*)(Cl + r0 * DD + col) = l01;
        *(__nv_bfloat162*)(Ch + r1 * DD + col) = h23;
        *(__nv_bfloat162*)(Cl + r1 * DD + col) = l23;
    }
}

// ---------------------------------------------------------------------------
// Launch
// ---------------------------------------------------------------------------
extern "C" void kernel_launch(void* const* d_in, const int* in_sizes, int n_in,
                              void* d_out, int out_size)
{
    const float* query = (const float*)d_in[0];
    const int*   mask  = (const int*)d_in[1];
    const float* Wq = (const float*)d_in[2];
    const float* bq = (const float*)d_in[3];
    const float* Wk = (const float*)d_in[4];
    const float* bk = (const float*)d_in[5];
    const float* Wv = (const float*)d_in[6];
    const float* bv = (const float*)d_in[7];
    const float* Wo = (const float*)d_in[8];
    const float* bo = (const float*)d_in[9];
    float* out = (float*)d_out;

    __nv_bfloat16 *xh, *xl, *wh, *wl, *qh, *ql, *kh, *kl, *vh, *vl, *ch, *cl, *bias;
    cudaGetSymbolAddress((void**)&xh, g_xh);
    cudaGetSymbolAddress((void**)&xl, g_xl);
    cudaGetSymbolAddress((void**)&wh, g_wh);
    cudaGetSymbolAddress((void**)&wl, g_wl);
    cudaGetSymbolAddress((void**)&qh, g_qh);
    cudaGetSymbolAddress((void**)&ql, g_ql);
    cudaGetSymbolAddress((void**)&kh, g_kh);
    cudaGetSymbolAddress((void**)&kl, g_kl);
    cudaGetSymbolAddress((void**)&vh, g_vh);
    cudaGetSymbolAddress((void**)&vl, g_vl);
    cudaGetSymbolAddress((void**)&ch, g_ch);
    cudaGetSymbolAddress((void**)&cl, g_cl);
    cudaGetSymbolAddress((void**)&bias, g_bias);

    cudaFuncSetAttribute(gemm_qkv_kernel,
                         cudaFuncAttributeMaxDynamicSharedMemorySize, SMEM_GG);
    cudaFuncSetAttribute(gemm_out_kernel,
                         cudaFuncAttributeMaxDynamicSharedMemorySize, SMEM_GG);
    cudaFuncSetAttribute(attn_mma_kernel,
                         cudaFuncAttributeMaxDynamicSharedMemorySize, SMEM_ATT);

    const int nX4 = MTOT * DD / 4;
    const int nW4 = DD * DD / 4;
    const int nM4 = BB * SS * SS / 4;

    split_kernel<<<(nX4 + 255) / 256, 256>>>(query, xh, xl, nX4);
    split_kernel<<<(nW4 + 255) / 256, 256>>>(Wq, wh, wl, nW4);
    split_kernel<<<(nW4 + 255) / 256, 256>>>(Wk, wh + (size_t)DD * DD,
                                             wl + (size_t)DD * DD, nW4);
    split_kernel<<<(nW4 + 255) / 256, 256>>>(Wv, wh + 2 * (size_t)DD * DD,
                                             wl + 2 * (size_t)DD * DD, nW4);
    maskbias_kernel<<<(nM4 + 255) / 256, 256>>>(mask, bias, nM4);

    dim3 qkvG(DD / 128, MTOT / 128, 3);     // (8, 32, 3)
    gemm_qkv_kernel<<<qkvG, 256, SMEM_GG>>>(xh, xl, wh, wl, bq, bk, bv,
                                            qh, ql, kh, kl, vh, vl);

    dim3 aG(SS / 128, BB * HH);             // (16, 32)
    attn_mma_kernel<<<aG, 256, SMEM_ATT>>>(qh, ql, kh, kl, vh, vl, bias, ch, cl);

    split_kernel<<<(nW4 + 255) / 256, 256>>>(Wo, wh, wl, nW4);
    dim3 oG(DD / 128, MTOT / 128);          // (8, 32)
    gemm_out_kernel<<<oG, 256, SMEM_GG>>>(ch, cl, wh, wl, bo, out);
}

// round 6
// speedup vs baseline: 3.6850x; 1.1142x over previous
#include <cuda_runtime.h>
#include <cuda_bf16.h>
#include <cstdint>
#include <math.h>

// Problem constants
#define BB   2
#define SS   2048
#define DD   1024
#define HH   16
#define DHH  64
#define MTOT (BB * SS)   // 4096

// ---------------------------------------------------------------------------
// Scratch (__device__ globals; allocation-free rule)
// ---------------------------------------------------------------------------
__device__ __nv_bfloat16 g_xh[(size_t)MTOT * DD];       // activation hi
__device__ __nv_bfloat16 g_xl[(size_t)MTOT * DD];       // activation lo
__device__ __nv_bfloat16 g_wh[3 * (size_t)DD * DD];     // weight hi (x3)
__device__ __nv_bfloat16 g_wl[3 * (size_t)DD * DD];     // weight lo (x3)
__device__ __nv_bfloat16 g_qh[(size_t)MTOT * DD];       // [B,H,S,64]
__device__ __nv_bfloat16 g_ql[(size_t)MTOT * DD];
__device__ __nv_bfloat16 g_kh[(size_t)MTOT * DD];
__device__ __nv_bfloat16 g_kl[(size_t)MTOT * DD];
__device__ __nv_bfloat16 g_vh[(size_t)MTOT * DD];
__device__ __nv_bfloat16 g_vl[(size_t)MTOT * DD];
__device__ __nv_bfloat16 g_ch[(size_t)MTOT * DD];       // ctx hi [MTOT][DD]
__device__ __nv_bfloat16 g_cl[(size_t)MTOT * DD];

// ---------------------------------------------------------------------------
// PTX helpers (classic tensor path: mma.sync / ldmatrix / cp.async)
// ---------------------------------------------------------------------------
__device__ __forceinline__ uint32_t smem_u32(const void* p) {
    uint32_t a;
    asm("{ .reg .u64 t; cvta.to.shared.u64 t, %1; cvt.u32.u64 %0, t; }"
        : "=r"(a) : "l"(p));
    return a;
}
#define CP_ASYNC16(dst, src) \
    asm volatile("cp.async.cg.shared.global [%0], [%1], 16;" :: "r"(dst), "l"(src))
#define CP_COMMIT() asm volatile("cp.async.commit_group;" ::: "memory")
#define CP_WAIT(n)  asm volatile("cp.async.wait_group %0;" :: "n"(n) : "memory")

__device__ __forceinline__ void ldm_x4(uint32_t* r, uint32_t addr) {
    asm volatile("ldmatrix.sync.aligned.m8n8.x4.shared.b16 {%0,%1,%2,%3}, [%4];"
        : "=r"(r[0]), "=r"(r[1]), "=r"(r[2]), "=r"(r[3]) : "r"(addr));
}
__device__ __forceinline__ void ldm_x4t(uint32_t* r, uint32_t addr) {
    asm volatile("ldmatrix.sync.aligned.m8n8.x4.trans.shared.b16 {%0,%1,%2,%3}, [%4];"
        : "=r"(r[0]), "=r"(r[1]), "=r"(r[2]), "=r"(r[3]) : "r"(addr));
}
__device__ __forceinline__ void mma16816(float* c, const uint32_t* a,
                                         const uint32_t* b) {
    asm volatile(
        "mma.sync.aligned.m16n8k16.row.col.f32.bf16.bf16.f32 "
        "{%0,%1,%2,%3}, {%4,%5,%6,%7}, {%8,%9}, {%0,%1,%2,%3};"
        : "+f"(c[0]), "+f"(c[1]), "+f"(c[2]), "+f"(c[3])
        : "r"(a[0]), "r"(a[1]), "r"(a[2]), "r"(a[3]), "r"(b[0]), "r"(b[1]));
}
__device__ __forceinline__ uint32_t bc32(__nv_bfloat162 v) {
    return *reinterpret_cast<uint32_t*>(&v);
}

// ---------------------------------------------------------------------------
// Split fp32 -> bf16 hi + lo
// ---------------------------------------------------------------------------
__global__ __launch_bounds__(256) void split_kernel(
    const float* __restrict__ x, __nv_bfloat16* __restrict__ hi,
    __nv_bfloat16* __restrict__ lo, int n4)
{
    int i = blockIdx.x * blockDim.x + threadIdx.x;
    if (i >= n4) return;
    float4 v = ((const float4*)x)[i];
    __nv_bfloat16 h0 = __float2bfloat16(v.x), h1 = __float2bfloat16(v.y);
    __nv_bfloat16 h2 = __float2bfloat16(v.z), h3 = __float2bfloat16(v.w);
    __nv_bfloat16 l0 = __float2bfloat16(v.x - __bfloat162float(h0));
    __nv_bfloat16 l1 = __float2bfloat16(v.y - __bfloat162float(h1));
    __nv_bfloat16 l2 = __float2bfloat16(v.z - __bfloat162float(h2));
    __nv_bfloat16 l3 = __float2bfloat16(v.w - __bfloat162float(h3));
    __nv_bfloat162* hp = (__nv_bfloat162*)(hi + (size_t)i * 4);
    __nv_bfloat162* lp = (__nv_bfloat162*)(lo + (size_t)i * 4);
    hp[0] = __nv_bfloat162(h0, h1); hp[1] = __nv_bfloat162(h2, h3);
    lp[0] = __nv_bfloat162(l0, l1); lp[1] = __nv_bfloat162(l2, l3);
}

// ---------------------------------------------------------------------------
// GEMM mainloop (bf16x3, CTA 128x128, BK=32, 3-stage cp.async, 1 sync/iter)
// ---------------------------------------------------------------------------
#define BKG      32
#define ROWH     40                       // padded halves per row (80B)
#define ROWB     (ROWH * 2)
#define TILE_BY  (128 * ROWB)             // 10240 B
#define OFF_AH   0
#define OFF_AL   (1 * TILE_BY)
#define OFF_WH   (2 * TILE_BY)
#define OFF_WL   (3 * TILE_BY)
#define BUF_BY   (4 * TILE_BY)            // 40960 B
#define SMEM_GG  (3 * BUF_BY)             // 122880 B

struct GemmAcc { float c[4][4][4]; };

__device__ __forceinline__ void gemm_mainloop(
    const __nv_bfloat16* Ah, const __nv_bfloat16* Al,
    const __nv_bfloat16* Bh, const __nv_bfloat16* Bl,
    int row0, int col0, uint32_t sb, GemmAcc& acc)
{
    const int tid  = threadIdx.x;
    const int lane = tid & 31;
    const int w    = tid >> 5;
    const int wm   = w & 1;
    const int wn   = w >> 1;

#pragma unroll
    for (int i = 0; i < 4; i++)
#pragma unroll
        for (int j = 0; j < 4; j++)
#pragma unroll
            for (int e = 0; e < 4; e++) acc.c[i][j][e] = 0.f;

    const int r0g = tid >> 2, s0 = tid & 3;
    const int r1g = (tid + 256) >> 2;
    const uint32_t sm0 = (uint32_t)(r0g * ROWB + s0 * 16);
    const uint32_t sm1 = (uint32_t)(r1g * ROWB + s0 * 16);

    // A frags: x4 at (row 16-group, k-half by lane>>4)
    const uint32_t aoff = (uint32_t)((lane & 15) * ROWB + ((lane >> 4) & 1) * 16);
    // B frags: x4 covering n-pair x k-halves
    const uint32_t boff = (uint32_t)(((((lane >> 4) & 1) * 8) + (lane & 7)) * ROWB
                                     + ((lane >> 3) & 1) * 16);

    auto issue = [&](int cidx) {
        const uint32_t bb = sb + (uint32_t)(cidx % 3) * BUF_BY;
        const int kc = cidx * BKG;
        CP_ASYNC16(bb + OFF_AH + sm0, Ah + (size_t)(row0 + r0g) * DD + kc + s0 * 8);
        CP_ASYNC16(bb + OFF_AL + sm0, Al + (size_t)(row0 + r0g) * DD + kc + s0 * 8);
        CP_ASYNC16(bb + OFF_WH + sm0, Bh + (size_t)(col0 + r0g) * DD + kc + s0 * 8);
        CP_ASYNC16(bb + OFF_WL + sm0, Bl + (size_t)(col0 + r0g) * DD + kc + s0 * 8);
        CP_ASYNC16(bb + OFF_AH + sm1, Ah + (size_t)(row0 + r1g) * DD + kc + s0 * 8);
        CP_ASYNC16(bb + OFF_AL + sm1, Al + (size_t)(row0 + r1g) * DD + kc + s0 * 8);
        CP_ASYNC16(bb + OFF_WH + sm1, Bh + (size_t)(col0 + r1g) * DD + kc + s0 * 8);
        CP_ASYNC16(bb + OFF_WL + sm1, Bl + (size_t)(col0 + r1g) * DD + kc + s0 * 8);
    };

    const int NCH = DD / BKG;   // 32
    issue(0); CP_COMMIT();
    issue(1); CP_COMMIT();

    for (int cidx = 0; cidx < NCH; cidx++) {
        CP_WAIT(1);
        __syncthreads();

        const uint32_t bb = sb + (uint32_t)(cidx % 3) * BUF_BY;
#pragma unroll
        for (int ks = 0; ks < 2; ks++) {
            const uint32_t k0b = (uint32_t)(ks * 32);
            uint32_t ah[4][4], al[4][4], bh[4][2], bl[4][2];
#pragma unroll
            for (int i = 0; i < 4; i++) {
                const uint32_t ao = (uint32_t)((wm * 64 + i * 16) * ROWB)
                                  + aoff + k0b;
                ldm_x4(ah[i], bb + OFF_AH + ao);
                ldm_x4(al[i], bb + OFF_AL + ao);
            }
#pragma unroll
            for (int jp = 0; jp < 2; jp++) {
                const uint32_t bo = (uint32_t)((wn * 32 + jp * 16) * ROWB)
                                  + boff + k0b;
                uint32_t th[4], tl[4];
                ldm_x4(th, bb + OFF_WH + bo);
                ldm_x4(tl, bb + OFF_WL + bo);
                bh[jp*2][0] = th[0]; bh[jp*2][1] = th[1];
                bh[jp*2+1][0] = th[2]; bh[jp*2+1][1] = th[3];
                bl[jp*2][0] = tl[0]; bl[jp*2][1] = tl[1];
                bl[jp*2+1][0] = tl[2]; bl[jp*2+1][1] = tl[3];
            }
#pragma unroll
            for (int i = 0; i < 4; i++)
#pragma unroll
                for (int j = 0; j < 4; j++) {
                    mma16816(acc.c[i][j], ah[i], bh[j]);
                    mma16816(acc.c[i][j], ah[i], bl[j]);
                    mma16816(acc.c[i][j], al[i], bh[j]);
                }
        }
        if (cidx + 2 < NCH) issue(cidx + 2);
        CP_COMMIT();
    }
}

// ---- final GEMM: fp32 out = acc + bias (Wo path)
__global__ __launch_bounds__(256, 1)
void gemm_out_kernel(const __nv_bfloat16* __restrict__ Ah,
                     const __nv_bfloat16* __restrict__ Al,
                     const __nv_bfloat16* __restrict__ Bh,
                     const __nv_bfloat16* __restrict__ Bl,
                     const float* __restrict__ bias,
                     float* __restrict__ out)
{
    extern __shared__ char smem[];
    const uint32_t sb = smem_u32(smem);
    const int lane = threadIdx.x & 31;
    const int w    = threadIdx.x >> 5;
    const int wm = w & 1, wn = w >> 1;
    const int row0 = blockIdx.y * 128, col0 = blockIdx.x * 128;

    GemmAcc acc;
    gemm_mainloop(Ah, Al, Bh, Bl, row0, col0, sb, acc);

    const int g = lane >> 2, tq = lane & 3;
#pragma unroll
    for (int i = 0; i < 4; i++) {
        const int mrow = row0 + wm * 64 + i * 16 + g;
#pragma unroll
        for (int j = 0; j < 4; j++) {
            const int col = col0 + wn * 32 + j * 8 + tq * 2;
            const float b0 = bias[col], b1 = bias[col + 1];
            *(float2*)(out + (size_t)mrow * DD + col) =
                make_float2(acc.c[i][j][0] + b0, acc.c[i][j][1] + b1);
            *(float2*)(out + (size_t)(mrow + 8) * DD + col) =
                make_float2(acc.c[i][j][2] + b0, acc.c[i][j][3] + b1);
        }
    }
}

// ---- QKV GEMM: z selects weight/bias/alpha; splits to hi/lo [B,H,S,64]
__global__ __launch_bounds__(256, 1)
void gemm_qkv_kernel(const __nv_bfloat16* __restrict__ Ah,
                     const __nv_bfloat16* __restrict__ Al,
                     const __nv_bfloat16* __restrict__ WH,
                     const __nv_bfloat16* __restrict__ WL,
                     const float* __restrict__ bq, const float* __restrict__ bk,
                     const float* __restrict__ bv,
                     __nv_bfloat16* __restrict__ qh, __nv_bfloat16* __restrict__ ql,
                     __nv_bfloat16* __restrict__ kh, __nv_bfloat16* __restrict__ kl,
                     __nv_bfloat16* __restrict__ vh, __nv_bfloat16* __restrict__ vl)
{
    extern __shared__ char smem[];
    const uint32_t sb = smem_u32(smem);
    const int z = blockIdx.z;
    const __nv_bfloat16* Bh = WH + (size_t)z * DD * DD;
    const __nv_bfloat16* Bl = WL + (size_t)z * DD * DD;
    const float* bias = (z == 0) ? bq : (z == 1) ? bk : bv;
    __nv_bfloat16* Oh = (z == 0) ? qh : (z == 1) ? kh : vh;
    __nv_bfloat16* Ol = (z == 0) ? ql : (z == 1) ? kl : vl;
    const float alpha = (z == 0) ? 0.125f : 1.0f;

    const int lane = threadIdx.x & 31;
    const int w    = threadIdx.x >> 5;
    const int wm = w & 1, wn = w >> 1;
    const int row0 = blockIdx.y * 128, col0 = blockIdx.x * 128;

    GemmAcc acc;
    gemm_mainloop(Ah, Al, Bh, Bl, row0, col0, sb, acc);

    const int g = lane >> 2, tq = lane & 3;
#pragma unroll
    for (int i = 0; i < 4; i++) {
        const int m0r = row0 + wm * 64 + i * 16 + g;
#pragma unroll
        for (int j = 0; j < 4; j++) {
            const int col = col0 + wn * 32 + j * 8 + tq * 2;
            const float b0 = bias[col], b1 = bias[col + 1];
            const int h = col >> 6, d = col & 63;
#pragma unroll
            for (int half = 0; half < 2; half++) {
                const int m = m0r + half * 8;
                const int b = m >> 11, s = m & 2047;
                const float v0 = (acc.c[i][j][half * 2 + 0] + b0) * alpha;
                const float v1 = (acc.c[i][j][half * 2 + 1] + b1) * alpha;
                __nv_bfloat162 hp = __float22bfloat162_rn(make_float2(v0, v1));
                float2 hf = __bfloat1622float2(hp);
                __nv_bfloat162 lp = __float22bfloat162_rn(
                    make_float2(v0 - hf.x, v1 - hf.y));
                const size_t o = (((size_t)(b * HH + h) * SS + s) << 6) + d;
                *(__nv_bfloat162*)(Oh + o) = hp;
                *(__nv_bfloat162*)(Ol + o) = lp;
            }
        }
    }
}

// ---------------------------------------------------------------------------
// Flash attention via mma.sync, bf16x3. 3-stage KV pipeline, 1 sync/iter.
// CTA: 128 q-rows x one (b,h). Direct int32 mask select.
// ---------------------------------------------------------------------------
#define DPADB   144
#define QTILE_B (128 * DPADB)           // 18432
#define KVT_B   (64 * DPADB)            // 9216
#define AOFF_QH 0
#define AOFF_QL QTILE_B
#define AOFF_ST (2 * QTILE_B)
#define STAGE_B (4 * KVT_B)             // 36864
#define AOFF_KH 0
#define AOFF_KL (1 * KVT_B)
#define AOFF_VH (2 * KVT_B)
#define AOFF_VL (3 * KVT_B)
#define SMEM_ATT (2 * QTILE_B + 3 * STAGE_B)   // 147456

__global__ __launch_bounds__(256, 1)
void attn_mma_kernel(const __nv_bfloat16* __restrict__ Qh,
                     const __nv_bfloat16* __restrict__ Ql,
                     const __nv_bfloat16* __restrict__ Kh,
                     const __nv_bfloat16* __restrict__ Kl,
                     const __nv_bfloat16* __restrict__ Vh,
                     const __nv_bfloat16* __restrict__ Vl,
                     const int* __restrict__ mask,
                     __nv_bfloat16* __restrict__ Ch,
                     __nv_bfloat16* __restrict__ Cl)
{
    extern __shared__ char smem[];
    const uint32_t sb = smem_u32(smem);
    const int tid = threadIdx.x, lane = tid & 31, w = tid >> 5;
    const int bh = blockIdx.y, b = bh >> 4, h = bh & 15;
    const int q0 = blockIdx.x * 128;
    const size_t hoff = (size_t)bh * SS * 64;

    auto issue_kv = [&](int kt) {
        const uint32_t st = sb + AOFF_ST + (uint32_t)(kt % 3) * STAGE_B;
#pragma unroll
        for (int u = tid; u < 512; u += 256) {
            const int r = u >> 3, sg = u & 7;
            const uint32_t so = (uint32_t)(r * DPADB + sg * 16);
            const size_t go = hoff + (size_t)(kt * 64 + r) * 64 + sg * 8;
            CP_ASYNC16(st + AOFF_KH + so, Kh + go);
            CP_ASYNC16(st + AOFF_KL + so, Kl + go);
            CP_ASYNC16(st + AOFF_VH + so, Vh + go);
            CP_ASYNC16(st + AOFF_VL + so, Vl + go);
        }
    };

    // group 0: Q + KV stage 0; group 1: KV stage 1
    for (int u = tid; u < 1024; u += 256) {
        const int r = u >> 3, sg = u & 7;
        const uint32_t so = (uint32_t)(r * DPADB + sg * 16);
        const size_t go = hoff + (size_t)(q0 + r) * 64 + sg * 8;
        CP_ASYNC16(sb + AOFF_QH + so, Qh + go);
        CP_ASYNC16(sb + AOFF_QL + so, Ql + go);
    }
    issue_kv(0); CP_COMMIT();
    issue_kv(1); CP_COMMIT();
    CP_WAIT(1); __syncthreads();

    // Q fragments (persistent)
    uint32_t qfh[4][4], qfl[4][4];
    const uint32_t aoff = (uint32_t)((w * 16 + (lane & 15)) * DPADB
                                     + ((lane >> 4) & 1) * 16);
#pragma unroll
    for (int c = 0; c < 4; c++) {
        ldm_x4(qfh[c], sb + AOFF_QH + aoff + c * 32);
        ldm_x4(qfl[c], sb + AOFF_QL + aoff + c * 32);
    }

    float O[8][4];
#pragma unroll
    for (int j = 0; j < 8; j++)
#pragma unroll
        for (int e = 0; e < 4; e++) O[j][e] = 0.f;
    float m0 = -INFINITY, m1 = -INFINITY, l0 = 0.f, l1 = 0.f;

    const int qrow = q0 + w * 16 + (lane >> 2);
    const int* mp0 = mask + ((size_t)b * SS + qrow) * SS;
    const int* mp1 = mp0 + (size_t)8 * SS;
    const int tq2 = (lane & 3) * 2;

    // K frag x4: n-pair x k-half mapping
    const uint32_t koff = (uint32_t)(((((lane >> 4) & 1) * 8) + (lane & 7)) * DPADB
                                     + ((lane >> 3) & 1) * 16);
    // V frag x4 trans: 16 key-rows x two 8-col d groups
    const uint32_t voff = (uint32_t)((lane & 15) * DPADB + ((lane >> 4) & 1) * 16);

    for (int kt = 0; kt < 32; kt++) {
        if (kt) { CP_WAIT(1); __syncthreads(); }
        const uint32_t st = sb + AOFF_ST + (uint32_t)(kt % 3) * STAGE_B;

        // ---- scores S = Q.K^T (bf16x3), K frags via x4 (j pairs)
        float S[8][4];
#pragma unroll
        for (int j = 0; j < 8; j++)
#pragma unroll
            for (int e = 0; e < 4; e++) S[j][e] = 0.f;
#pragma unroll
        for (int c = 0; c < 4; c++)
#pragma unroll
            for (int jp = 0; jp < 4; jp++) {
                uint32_t th[4], tl[4];
                const uint32_t ko = (uint32_t)(jp * 16 * DPADB) + koff + c * 32;
                ldm_x4(th, st + AOFF_KH + ko);
                ldm_x4(tl, st + AOFF_KL + ko);
                mma16816(S[jp*2],   qfh[c], th);
                mma16816(S[jp*2],   qfh[c], tl);
                mma16816(S[jp*2],   qfl[c], th);
                mma16816(S[jp*2+1], qfh[c], th + 2);
                mma16816(S[jp*2+1], qfh[c], tl + 2);
                mma16816(S[jp*2+1], qfl[c], th + 2);
            }

        // ---- mask select + row max
        const int kt64 = kt * 64;
        float mx0 = -INFINITY, mx1 = -INFINITY;
#pragma unroll
        for (int j = 0; j < 8; j++) {
            const int kcol = kt64 + j * 8 + tq2;
            int2 ma = *(const int2*)(mp0 + kcol);
            int2 mb = *(const int2*)(mp1 + kcol);
            S[j][0] = ma.x ? -1e18f : S[j][0];
            S[j][1] = ma.y ? -1e18f : S[j][1];
            S[j][2] = mb.x ? -1e18f : S[j][2];
            S[j][3] = mb.y ? -1e18f : S[j][3];
            mx0 = fmaxf(mx0, fmaxf(S[j][0], S[j][1]));
            mx1 = fmaxf(mx1, fmaxf(S[j][2], S[j][3]));
        }
        mx0 = fmaxf(mx0, __shfl_xor_sync(0xFFFFFFFFu, mx0, 1));
        mx0 = fmaxf(mx0, __shfl_xor_sync(0xFFFFFFFFu, mx0, 2));
        mx1 = fmaxf(mx1, __shfl_xor_sync(0xFFFFFFFFu, mx1, 1));
        mx1 = fmaxf(mx1, __shfl_xor_sync(0xFFFFFFFFu, mx1, 2));

        const float mn0 = fmaxf(m0, mx0), mn1 = fmaxf(m1, mx1);
        const float cr0 = __expf(m0 - mn0), cr1 = __expf(m1 - mn1);
        m0 = mn0; m1 = mn1;
        l0 *= cr0; l1 *= cr1;
#pragma unroll
        for (int j = 0; j < 8; j++) {
            O[j][0] *= cr0; O[j][1] *= cr0;
            O[j][2] *= cr1; O[j][3] *= cr1;
        }

        // ---- exp + split P to bf16 hi/lo fragments
        uint32_t PH[8][2], PL[8][2];
#pragma unroll
        for (int j = 0; j < 8; j++) {
            const float p0 = __expf(S[j][0] - m0), p1 = __expf(S[j][1] - m0);
            const float p2 = __expf(S[j][2] - m1), p3 = __expf(S[j][3] - m1);
            l0 += p0 + p1; l1 += p2 + p3;
            __nv_bfloat162 h01 = __float22bfloat162_rn(make_float2(p0, p1));
            float2 hf01 = __bfloat1622float2(h01);
            __nv_bfloat162 l01 = __float22bfloat162_rn(
                make_float2(p0 - hf01.x, p1 - hf01.y));
            __nv_bfloat162 h23 = __float22bfloat162_rn(make_float2(p2, p3));
            float2 hf23 = __bfloat1622float2(h23);
            __nv_bfloat162 l23 = __float22bfloat162_rn(
                make_float2(p2 - hf23.x, p3 - hf23.y));
            PH[j][0] = bc32(h01); PH[j][1] = bc32(h23);
            PL[j][0] = bc32(l01); PL[j][1] = bc32(l23);
        }

        // ---- O += P.V (bf16x3), V frags via x4 trans (j pairs)
#pragma unroll
        for (int t = 0; t < 4; t++) {
            uint32_t ah[4] = { PH[2*t][0], PH[2*t][1], PH[2*t+1][0], PH[2*t+1][1] };
            uint32_t al[4] = { PL[2*t][0], PL[2*t][1], PL[2*t+1][0], PL[2*t+1][1] };
#pragma unroll
            for (int jp = 0; jp < 4; jp++) {
                uint32_t th[4], tl[4];
                const uint32_t vo = (uint32_t)(t * 16 * DPADB) + voff + jp * 32;
                ldm_x4t(th, st + AOFF_VH + vo);
                ldm_x4t(tl, st + AOFF_VL + vo);
                mma16816(O[jp*2],   ah, th);
                mma16816(O[jp*2],   ah, tl);
                mma16816(O[jp*2],   al, th);
                mma16816(O[jp*2+1], ah, th + 2);
                mma16816(O[jp*2+1], ah, tl + 2);
                mma16816(O[jp*2+1], al, th + 2);
            }
        }

        if (kt + 2 < 32) issue_kv(kt + 2);
        CP_COMMIT();
    }

    // ---- epilogue
    l0 += __shfl_xor_sync(0xFFFFFFFFu, l0, 1);
    l0 += __shfl_xor_sync(0xFFFFFFFFu, l0, 2);
    l1 += __shfl_xor_sync(0xFFFFFFFFu, l1, 1);
    l1 += __shfl_xor_sync(0xFFFFFFFFu, l1, 2);
    const float i0 = 1.f / l0, i1 = 1.f / l1;

    const size_t r0 = (size_t)(b * SS + qrow);
    const size_t r1 = r0 + 8;
    const int colb = h * 64 + tq2;
#pragma unroll
    for (int j = 0; j < 8; j++) {
        const int col = colb + j * 8;
        const float v0 = O[j][0] * i0, v1 = O[j][1] * i0;
        const float v2 = O[j][2] * i1, v3 = O[j][3] * i1;
        __nv_bfloat162 h01 = __float22bfloat162_rn(make_float2(v0, v1));
        float2 hf01 = __bfloat1622float2(h01);
        __nv_bfloat162 l01 = __float22bfloat162_rn(make_float2(v0 - hf01.x, v1 - hf01.y));
        __nv_bfloat162 h23 = __float22bfloat162_rn(make_float2(v2, v3));
        float2 hf23 = __bfloat1622float2(h23);
        __nv_bfloat162 l23 = __float22bfloat162_rn(make_float2(v2 - hf23.x, v3 - hf23.y));
        *(__nv_bfloat162*)(Ch + r0 * DD + col) = h01;
        *(__nv_bfloat162*)(Cl + r0 * DD + col) = l01;
        *(__nv_bfloat162*)(Ch + r1 * DD + col) = h23;
        *(__nv_bfloat162*)(Cl + r1 * DD + col) = l23;
    }
}

// ---------------------------------------------------------------------------
// Launch
// ---------------------------------------------------------------------------
extern "C" void kernel_launch(void* const* d_in, const int* in_sizes, int n_in,
                              void* d_out, int out_size)
{
    const float* query = (const float*)d_in[0];
    const int*   mask  = (const int*)d_in[1];
    const float* Wq = (const float*)d_in[2];
    const float* bq = (const float*)d_in[3];
    const float* Wk = (const float*)d_in[4];
    const float* bk = (const float*)d_in[5];
    const float* Wv = (const float*)d_in[6];
    const float* bv = (const float*)d_in[7];
    const float* Wo = (const float*)d_in[8];
    const float* bo = (const float*)d_in[9];
    float* out = (float*)d_out;

    __nv_bfloat16 *xh, *xl, *wh, *wl, *qh, *ql, *kh, *kl, *vh, *vl, *ch, *cl;
    cudaGetSymbolAddress((void**)&xh, g_xh);
    cudaGetSymbolAddress((void**)&xl, g_xl);
    cudaGetSymbolAddress((void**)&wh, g_wh);
    cudaGetSymbolAddress((void**)&wl, g_wl);
    cudaGetSymbolAddress((void**)&qh, g_qh);
    cudaGetSymbolAddress((void**)&ql, g_ql);
    cudaGetSymbolAddress((void**)&kh, g_kh);
    cudaGetSymbolAddress((void**)&kl, g_kl);
    cudaGetSymbolAddress((void**)&vh, g_vh);
    cudaGetSymbolAddress((void**)&vl, g_vl);
    cudaGetSymbolAddress((void**)&ch, g_ch);
    cudaGetSymbolAddress((void**)&cl, g_cl);

    cudaFuncSetAttribute(gemm_qkv_kernel,
                         cudaFuncAttributeMaxDynamicSharedMemorySize, SMEM_GG);
    cudaFuncSetAttribute(gemm_out_kernel,
                         cudaFuncAttributeMaxDynamicSharedMemorySize, SMEM_GG);
    cudaFuncSetAttribute(attn_mma_kernel,
                         cudaFuncAttributeMaxDynamicSharedMemorySize, SMEM_ATT);

    const int nX4 = MTOT * DD / 4;
    const int nW4 = DD * DD / 4;

    split_kernel<<<(nX4 + 255) / 256, 256>>>(query, xh, xl, nX4);
    split_kernel<<<(nW4 + 255) / 256, 256>>>(Wq, wh, wl, nW4);
    split_kernel<<<(nW4 + 255) / 256, 256>>>(Wk, wh + (size_t)DD * DD,
                                             wl + (size_t)DD * DD, nW4);
    split_kernel<<<(nW4 + 255) / 256, 256>>>(Wv, wh + 2 * (size_t)DD * DD,
                                             wl + 2 * (size_t)DD * DD, nW4);

    dim3 qkvG(DD / 128, MTOT / 128, 3);     // (8, 32, 3)
    gemm_qkv_kernel<<<qkvG, 256, SMEM_GG>>>(xh, xl, wh, wl, bq, bk, bv,
                                            qh, ql, kh, kl, vh, vl);

    dim3 aG(SS / 128, BB * HH);             // (16, 32)
    attn_mma_kernel<<<aG, 256, SMEM_ATT>>>(qh, ql, kh, kl, vh, vl, mask, ch, cl);

    split_kernel<<<(nW4 + 255) / 256, 256>>>(Wo, wh, wl, nW4);
    dim3 oG(DD / 128, MTOT / 128);          // (8, 32)
    gemm_out_kernel<<<oG, 256, SMEM_GG>>>(ch, cl, wh, wl, bo, out);
}

// round 7
// speedup vs baseline: 3.7416x; 1.0154x over previous
#include <cuda_runtime.h>
#include <cuda_bf16.h>
#include <cstdint>
#include <math.h>

// Problem constants
#define BB   2
#define SS   2048
#define DD   1024
#define HH   16
#define DHH  64
#define MTOT (BB * SS)   // 4096

// ---------------------------------------------------------------------------
// Scratch (__device__ globals; allocation-free rule)
// ---------------------------------------------------------------------------
__device__ __nv_bfloat16 g_xh[(size_t)MTOT * DD];
__device__ __nv_bfloat16 g_xl[(size_t)MTOT * DD];
__device__ __nv_bfloat16 g_wh[3 * (size_t)DD * DD];
__device__ __nv_bfloat16 g_wl[3 * (size_t)DD * DD];
__device__ __nv_bfloat16 g_qh[(size_t)MTOT * DD];       // [B,H,S,64]
__device__ __nv_bfloat16 g_ql[(size_t)MTOT * DD];
__device__ __nv_bfloat16 g_kh[(size_t)MTOT * DD];
__device__ __nv_bfloat16 g_kl[(size_t)MTOT * DD];
__device__ __nv_bfloat16 g_vh[(size_t)MTOT * DD];
__device__ __nv_bfloat16 g_vl[(size_t)MTOT * DD];
__device__ __nv_bfloat16 g_ch[(size_t)MTOT * DD];
__device__ __nv_bfloat16 g_cl[(size_t)MTOT * DD];

// ---------------------------------------------------------------------------
// PTX helpers
// ---------------------------------------------------------------------------
__device__ __forceinline__ uint32_t smem_u32(const void* p) {
    uint32_t a;
    asm("{ .reg .u64 t; cvta.to.shared.u64 t, %1; cvt.u32.u64 %0, t; }"
        : "=r"(a) : "l"(p));
    return a;
}
#define CP_ASYNC16(dst, src) \
    asm volatile("cp.async.cg.shared.global [%0], [%1], 16;" :: "r"(dst), "l"(src))
#define CP_COMMIT() asm volatile("cp.async.commit_group;" ::: "memory")
#define CP_WAIT(n)  asm volatile("cp.async.wait_group %0;" :: "n"(n) : "memory")

__device__ __forceinline__ void ldm_x4(uint32_t* r, uint32_t addr) {
    asm volatile("ldmatrix.sync.aligned.m8n8.x4.shared.b16 {%0,%1,%2,%3}, [%4];"
        : "=r"(r[0]), "=r"(r[1]), "=r"(r[2]), "=r"(r[3]) : "r"(addr));
}
__device__ __forceinline__ void ldm_x4t(uint32_t* r, uint32_t addr) {
    asm volatile("ldmatrix.sync.aligned.m8n8.x4.trans.shared.b16 {%0,%1,%2,%3}, [%4];"
        : "=r"(r[0]), "=r"(r[1]), "=r"(r[2]), "=r"(r[3]) : "r"(addr));
}
__device__ __forceinline__ void mma16816(float* c, const uint32_t* a,
                                         const uint32_t* b) {
    asm volatile(
        "mma.sync.aligned.m16n8k16.row.col.f32.bf16.bf16.f32 "
        "{%0,%1,%2,%3}, {%4,%5,%6,%7}, {%8,%9}, {%0,%1,%2,%3};"
        : "+f"(c[0]), "+f"(c[1]), "+f"(c[2]), "+f"(c[3])
        : "r"(a[0]), "r"(a[1]), "r"(a[2]), "r"(a[3]), "r"(b[0]), "r"(b[1]));
}
__device__ __forceinline__ uint32_t bc32(__nv_bfloat162 v) {
    return *reinterpret_cast<uint32_t*>(&v);
}

// ---------------------------------------------------------------------------
// Split fp32 -> bf16 hi + lo
// ---------------------------------------------------------------------------
__global__ __launch_bounds__(256) void split_kernel(
    const float* __restrict__ x, __nv_bfloat16* __restrict__ hi,
    __nv_bfloat16* __restrict__ lo, int n4)
{
    int i = blockIdx.x * blockDim.x + threadIdx.x;
    if (i >= n4) return;
    float4 v = ((const float4*)x)[i];
    __nv_bfloat16 h0 = __float2bfloat16(v.x), h1 = __float2bfloat16(v.y);
    __nv_bfloat16 h2 = __float2bfloat16(v.z), h3 = __float2bfloat16(v.w);
    __nv_bfloat16 l0 = __float2bfloat16(v.x - __bfloat162float(h0));
    __nv_bfloat16 l1 = __float2bfloat16(v.y - __bfloat162float(h1));
    __nv_bfloat16 l2 = __float2bfloat16(v.z - __bfloat162float(h2));
    __nv_bfloat16 l3 = __float2bfloat16(v.w - __bfloat162float(h3));
    __nv_bfloat162* hp = (__nv_bfloat162*)(hi + (size_t)i * 4);
    __nv_bfloat162* lp = (__nv_bfloat162*)(lo + (size_t)i * 4);
    hp[0] = __nv_bfloat162(h0, h1); hp[1] = __nv_bfloat162(h2, h3);
    lp[0] = __nv_bfloat162(l0, l1); lp[1] = __nv_bfloat162(l2, l3);
}

// ---------------------------------------------------------------------------
// GEMM mainloop: bf16x3, CTA 128x128, BK=64, 3-stage cp.async, 1 sync/chunk.
// Rows padded to 144B (16B rotation per row -> conflict-free ldmatrix).
// ---------------------------------------------------------------------------
#define GROWB    144
#define GTILE_B  (128 * GROWB)            // 18432
#define GOFF_AH  0
#define GOFF_AL  (1 * GTILE_B)
#define GOFF_WH  (2 * GTILE_B)
#define GOFF_WL  (3 * GTILE_B)
#define GSTAGE_B (4 * GTILE_B)            // 73728
#define SMEM_GG  (3 * GSTAGE_B)           // 221184

struct GemmAcc { float c[4][4][4]; };

__device__ __forceinline__ void gemm_mainloop(
    const __nv_bfloat16* Ah, const __nv_bfloat16* Al,
    const __nv_bfloat16* Bh, const __nv_bfloat16* Bl,
    int row0, int col0, uint32_t sb, GemmAcc& acc)
{
    const int tid  = threadIdx.x;
    const int lane = tid & 31;
    const int w    = tid >> 5;
    const int wm   = w & 1;
    const int wn   = w >> 1;

#pragma unroll
    for (int i = 0; i < 4; i++)
#pragma unroll
        for (int j = 0; j < 4; j++)
#pragma unroll
            for (int e = 0; e < 4; e++) acc.c[i][j][e] = 0.f;

    const uint32_t aoff = (uint32_t)((lane & 15) * GROWB + ((lane >> 4) & 1) * 16);
    const uint32_t boff = (uint32_t)(((((lane >> 4) & 1) * 8) + (lane & 7)) * GROWB
                                     + ((lane >> 3) & 1) * 16);

    auto issue = [&](int cidx) {
        const uint32_t bb = sb + (uint32_t)(cidx % 3) * GSTAGE_B;
        const int kc = cidx * 64;
#pragma unroll
        for (int i = 0; i < 4; i++) {
            const int u = tid + i * 256;
            const int row = u >> 3, sg = u & 7;
            const uint32_t so = (uint32_t)(row * GROWB + sg * 16);
            CP_ASYNC16(bb + GOFF_AH + so, Ah + (size_t)(row0 + row) * DD + kc + sg * 8);
            CP_ASYNC16(bb + GOFF_AL + so, Al + (size_t)(row0 + row) * DD + kc + sg * 8);
            CP_ASYNC16(bb + GOFF_WH + so, Bh + (size_t)(col0 + row) * DD + kc + sg * 8);
            CP_ASYNC16(bb + GOFF_WL + so, Bl + (size_t)(col0 + row) * DD + kc + sg * 8);
        }
    };

    const int NCH = DD / 64;   // 16
    issue(0); CP_COMMIT();
    issue(1); CP_COMMIT();

    for (int cidx = 0; cidx < NCH; cidx++) {
        CP_WAIT(1);
        __syncthreads();

        const uint32_t bb = sb + (uint32_t)(cidx % 3) * GSTAGE_B;
#pragma unroll
        for (int ks = 0; ks < 4; ks++) {
            const uint32_t k0b = (uint32_t)(ks * 32);
            uint32_t ah[4][4], al[4][4], bh[4][2], bl[4][2];
#pragma unroll
            for (int i = 0; i < 4; i++) {
                const uint32_t ao = (uint32_t)((wm * 64 + i * 16) * GROWB)
                                  + aoff + k0b;
                ldm_x4(ah[i], bb + GOFF_AH + ao);
                ldm_x4(al[i], bb + GOFF_AL + ao);
            }
#pragma unroll
            for (int jp = 0; jp < 2; jp++) {
                const uint32_t bo = (uint32_t)((wn * 32 + jp * 16) * GROWB)
                                  + boff + k0b;
                uint32_t th[4], tl[4];
                ldm_x4(th, bb + GOFF_WH + bo);
                ldm_x4(tl, bb + GOFF_WL + bo);
                bh[jp*2][0] = th[0]; bh[jp*2][1] = th[1];
                bh[jp*2+1][0] = th[2]; bh[jp*2+1][1] = th[3];
                bl[jp*2][0] = tl[0]; bl[jp*2][1] = tl[1];
                bl[jp*2+1][0] = tl[2]; bl[jp*2+1][1] = tl[3];
            }
#pragma unroll
            for (int i = 0; i < 4; i++)
#pragma unroll
                for (int j = 0; j < 4; j++) {
                    mma16816(acc.c[i][j], ah[i], bh[j]);
                    mma16816(acc.c[i][j], ah[i], bl[j]);
                    mma16816(acc.c[i][j], al[i], bh[j]);
                }
        }
        if (cidx + 2 < NCH) issue(cidx + 2);
        CP_COMMIT();
    }
}

// ---- final GEMM: fp32 out = acc + bias (Wo path)
__global__ __launch_bounds__(256, 1)
void gemm_out_kernel(const __nv_bfloat16* __restrict__ Ah,
                     const __nv_bfloat16* __restrict__ Al,
                     const __nv_bfloat16* __restrict__ Bh,
                     const __nv_bfloat16* __restrict__ Bl,
                     const float* __restrict__ bias,
                     float* __restrict__ out)
{
    extern __shared__ char smem[];
    const uint32_t sb = smem_u32(smem);
    const int lane = threadIdx.x & 31;
    const int w    = threadIdx.x >> 5;
    const int wm = w & 1, wn = w >> 1;
    const int row0 = blockIdx.y * 128, col0 = blockIdx.x * 128;

    GemmAcc acc;
    gemm_mainloop(Ah, Al, Bh, Bl, row0, col0, sb, acc);

    const int g = lane >> 2, tq = lane & 3;
#pragma unroll
    for (int i = 0; i < 4; i++) {
        const int mrow = row0 + wm * 64 + i * 16 + g;
#pragma unroll
        for (int j = 0; j < 4; j++) {
            const int col = col0 + wn * 32 + j * 8 + tq * 2;
            const float b0 = bias[col], b1 = bias[col + 1];
            *(float2*)(out + (size_t)mrow * DD + col) =
                make_float2(acc.c[i][j][0] + b0, acc.c[i][j][1] + b1);
            *(float2*)(out + (size_t)(mrow + 8) * DD + col) =
                make_float2(acc.c[i][j][2] + b0, acc.c[i][j][3] + b1);
        }
    }
}

// ---- QKV GEMM: z selects weight/bias/alpha; splits to hi/lo [B,H,S,64]
__global__ __launch_bounds__(256, 1)
void gemm_qkv_kernel(const __nv_bfloat16* __restrict__ Ah,
                     const __nv_bfloat16* __restrict__ Al,
                     const __nv_bfloat16* __restrict__ WH,
                     const __nv_bfloat16* __restrict__ WL,
                     const float* __restrict__ bq, const float* __restrict__ bk,
                     const float* __restrict__ bv,
                     __nv_bfloat16* __restrict__ qh, __nv_bfloat16* __restrict__ ql,
                     __nv_bfloat16* __restrict__ kh, __nv_bfloat16* __restrict__ kl,
                     __nv_bfloat16* __restrict__ vh, __nv_bfloat16* __restrict__ vl)
{
    extern __shared__ char smem[];
    const uint32_t sb = smem_u32(smem);
    const int z = blockIdx.z;
    const __nv_bfloat16* Bh = WH + (size_t)z * DD * DD;
    const __nv_bfloat16* Bl = WL + (size_t)z * DD * DD;
    const float* bias = (z == 0) ? bq : (z == 1) ? bk : bv;
    __nv_bfloat16* Oh = (z == 0) ? qh : (z == 1) ? kh : vh;
    __nv_bfloat16* Ol = (z == 0) ? ql : (z == 1) ? kl : vl;
    const float alpha = (z == 0) ? 0.125f : 1.0f;

    const int lane = threadIdx.x & 31;
    const int w    = threadIdx.x >> 5;
    const int wm = w & 1, wn = w >> 1;
    const int row0 = blockIdx.y * 128, col0 = blockIdx.x * 128;

    GemmAcc acc;
    gemm_mainloop(Ah, Al, Bh, Bl, row0, col0, sb, acc);

    const int g = lane >> 2, tq = lane & 3;
#pragma unroll
    for (int i = 0; i < 4; i++) {
        const int m0r = row0 + wm * 64 + i * 16 + g;
#pragma unroll
        for (int j = 0; j < 4; j++) {
            const int col = col0 + wn * 32 + j * 8 + tq * 2;
            const float b0 = bias[col], b1 = bias[col + 1];
            const int h = col >> 6, d = col & 63;
#pragma unroll
            for (int half = 0; half < 2; half++) {
                const int m = m0r + half * 8;
                const int b = m >> 11, s = m & 2047;
                const float v0 = (acc.c[i][j][half * 2 + 0] + b0) * alpha;
                const float v1 = (acc.c[i][j][half * 2 + 1] + b1) * alpha;
                __nv_bfloat162 hp = __float22bfloat162_rn(make_float2(v0, v1));
                float2 hf = __bfloat1622float2(hp);
                __nv_bfloat162 lp = __float22bfloat162_rn(
                    make_float2(v0 - hf.x, v1 - hf.y));
                const size_t o = (((size_t)(b * HH + h) * SS + s) << 6) + d;
                *(__nv_bfloat162*)(Oh + o) = hp;
                *(__nv_bfloat162*)(Ol + o) = lp;
            }
        }
    }
}

// ---------------------------------------------------------------------------
// Flash attention, software-pipelined: QK(kt+1) overlaps softmax(kt).
// 4-stage KV ring, S double-buffered in regs, 1 sync/iter.
// ---------------------------------------------------------------------------
#define DPADB    144
#define QTILE_B  (128 * DPADB)          // 18432
#define KVT_B    (64 * DPADB)           // 9216
#define AOFF_QH  0
#define AOFF_QL  QTILE_B
#define AOFF_ST  (2 * QTILE_B)
#define STAGE_B  (4 * KVT_B)            // 36864
#define AOFF_KH  0
#define AOFF_KL  (1 * KVT_B)
#define AOFF_VH  (2 * KVT_B)
#define AOFF_VL  (3 * KVT_B)
#define SMEM_ATT (2 * QTILE_B + 4 * STAGE_B)   // 184320

__global__ __launch_bounds__(256, 1)
void attn_mma_kernel(const __nv_bfloat16* __restrict__ Qh,
                     const __nv_bfloat16* __restrict__ Ql,
                     const __nv_bfloat16* __restrict__ Kh,
                     const __nv_bfloat16* __restrict__ Kl,
                     const __nv_bfloat16* __restrict__ Vh,
                     const __nv_bfloat16* __restrict__ Vl,
                     const int* __restrict__ mask,
                     __nv_bfloat16* __restrict__ Ch,
                     __nv_bfloat16* __restrict__ Cl)
{
    extern __shared__ char smem[];
    const uint32_t sb = smem_u32(smem);
    const int tid = threadIdx.x, lane = tid & 31, w = tid >> 5;
    const int bh = blockIdx.y, b = bh >> 4, h = bh & 15;
    const int q0 = blockIdx.x * 128;
    const size_t hoff = (size_t)bh * SS * 64;

    auto issue_kv = [&](int kt) {
        const uint32_t st = sb + AOFF_ST + (uint32_t)(kt & 3) * STAGE_B;
#pragma unroll
        for (int u = tid; u < 512; u += 256) {
            const int r = u >> 3, sg = u & 7;
            const uint32_t so = (uint32_t)(r * DPADB + sg * 16);
            const size_t go = hoff + (size_t)(kt * 64 + r) * 64 + sg * 8;
            CP_ASYNC16(st + AOFF_KH + so, Kh + go);
            CP_ASYNC16(st + AOFF_KL + so, Kl + go);
            CP_ASYNC16(st + AOFF_VH + so, Vh + go);
            CP_ASYNC16(st + AOFF_VL + so, Vl + go);
        }
    };

    for (int u = tid; u < 1024; u += 256) {
        const int r = u >> 3, sg = u & 7;
        const uint32_t so = (uint32_t)(r * DPADB + sg * 16);
        const size_t go = hoff + (size_t)(q0 + r) * 64 + sg * 8;
        CP_ASYNC16(sb + AOFF_QH + so, Qh + go);
        CP_ASYNC16(sb + AOFF_QL + so, Ql + go);
    }
    issue_kv(0); CP_COMMIT();
    issue_kv(1); CP_COMMIT();
    issue_kv(2); CP_COMMIT();
    CP_WAIT(2); __syncthreads();   // Q + stage 0 ready

    // Q fragments (persistent)
    uint32_t qfh[4][4], qfl[4][4];
    const uint32_t aoff = (uint32_t)((w * 16 + (lane & 15)) * DPADB
                                     + ((lane >> 4) & 1) * 16);
#pragma unroll
    for (int c = 0; c < 4; c++) {
        ldm_x4(qfh[c], sb + AOFF_QH + aoff + c * 32);
        ldm_x4(qfl[c], sb + AOFF_QL + aoff + c * 32);
    }

    const uint32_t koff = (uint32_t)(((((lane >> 4) & 1) * 8) + (lane & 7)) * DPADB
                                     + ((lane >> 3) & 1) * 16);
    const uint32_t voff = (uint32_t)((lane & 15) * DPADB + ((lane >> 4) & 1) * 16);

    // QK into S for key-tile kt (stage kt&3)
    auto computeQK = [&](float (&S)[8][4], int kt) {
        const uint32_t st = sb + AOFF_ST + (uint32_t)(kt & 3) * STAGE_B;
#pragma unroll
        for (int j = 0; j < 8; j++)
#pragma unroll
            for (int e = 0; e < 4; e++) S[j][e] = 0.f;
#pragma unroll
        for (int c = 0; c < 4; c++)
#pragma unroll
            for (int jp = 0; jp < 4; jp++) {
                uint32_t th[4], tl[4];
                const uint32_t ko = (uint32_t)(jp * 16 * DPADB) + koff + c * 32;
                ldm_x4(th, st + AOFF_KH + ko);
                ldm_x4(tl, st + AOFF_KL + ko);
                mma16816(S[jp*2],   qfh[c], th);
                mma16816(S[jp*2],   qfh[c], tl);
                mma16816(S[jp*2],   qfl[c], th);
                mma16816(S[jp*2+1], qfh[c], th + 2);
                mma16816(S[jp*2+1], qfh[c], tl + 2);
                mma16816(S[jp*2+1], qfl[c], th + 2);
            }
    };

    float O[8][4];
#pragma unroll
    for (int j = 0; j < 8; j++)
#pragma unroll
        for (int e = 0; e < 4; e++) O[j][e] = 0.f;
    float m0 = -INFINITY, m1 = -INFINITY, l0 = 0.f, l1 = 0.f;

    const int qrow = q0 + w * 16 + (lane >> 2);
    const int* mp0 = mask + ((size_t)b * SS + qrow) * SS;
    const int* mp1 = mp0 + (size_t)8 * SS;
    const int tq2 = (lane & 3) * 2;

    float S[2][8][4];
    computeQK(S[0], 0);

#pragma unroll 2
    for (int kt = 0; kt < 32; kt++) {
        const int cur = kt & 1, nxt = cur ^ 1;
        CP_WAIT(1);
        __syncthreads();

        // prefetch mask (gmem latency hidden under QK MMAs)
        int2 ma[8], mb[8];
        const int kt64 = kt * 64;
#pragma unroll
        for (int j = 0; j < 8; j++) {
            const int kcol = kt64 + j * 8 + tq2;
            ma[j] = *(const int2*)(mp0 + kcol);
            mb[j] = *(const int2*)(mp1 + kcol);
        }

        // ---- QK(kt+1): fills tensor pipe while softmax ALU below executes
        if (kt + 1 < 32) computeQK(S[nxt], kt + 1);

        // ---- softmax(kt) on S[cur]
        float mx0 = -INFINITY, mx1 = -INFINITY;
#pragma unroll
        for (int j = 0; j < 8; j++) {
            S[cur][j][0] = ma[j].x ? -1e18f : S[cur][j][0];
            S[cur][j][1] = ma[j].y ? -1e18f : S[cur][j][1];
            S[cur][j][2] = mb[j].x ? -1e18f : S[cur][j][2];
            S[cur][j][3] = mb[j].y ? -1e18f : S[cur][j][3];
            mx0 = fmaxf(mx0, fmaxf(S[cur][j][0], S[cur][j][1]));
            mx1 = fmaxf(mx1, fmaxf(S[cur][j][2], S[cur][j][3]));
        }
        mx0 = fmaxf(mx0, __shfl_xor_sync(0xFFFFFFFFu, mx0, 1));
        mx0 = fmaxf(mx0, __shfl_xor_sync(0xFFFFFFFFu, mx0, 2));
        mx1 = fmaxf(mx1, __shfl_xor_sync(0xFFFFFFFFu, mx1, 1));
        mx1 = fmaxf(mx1, __shfl_xor_sync(0xFFFFFFFFu, mx1, 2));

        const float mn0 = fmaxf(m0, mx0), mn1 = fmaxf(m1, mx1);
        const float cr0 = __expf(m0 - mn0), cr1 = __expf(m1 - mn1);
        m0 = mn0; m1 = mn1;
        l0 *= cr0; l1 *= cr1;
#pragma unroll
        for (int j = 0; j < 8; j++) {
            O[j][0] *= cr0; O[j][1] *= cr0;
            O[j][2] *= cr1; O[j][3] *= cr1;
        }

        uint32_t PH[8][2], PL[8][2];
#pragma unroll
        for (int j = 0; j < 8; j++) {
            const float p0 = __expf(S[cur][j][0] - m0);
            const float p1 = __expf(S[cur][j][1] - m0);
            const float p2 = __expf(S[cur][j][2] - m1);
            const float p3 = __expf(S[cur][j][3] - m1);
            l0 += p0 + p1; l1 += p2 + p3;
            __nv_bfloat162 h01 = __float22bfloat162_rn(make_float2(p0, p1));
            float2 hf01 = __bfloat1622float2(h01);
            __nv_bfloat162 l01 = __float22bfloat162_rn(
                make_float2(p0 - hf01.x, p1 - hf01.y));
            __nv_bfloat162 h23 = __float22bfloat162_rn(make_float2(p2, p3));
            float2 hf23 = __bfloat1622float2(h23);
            __nv_bfloat162 l23 = __float22bfloat162_rn(
                make_float2(p2 - hf23.x, p3 - hf23.y));
            PH[j][0] = bc32(h01); PH[j][1] = bc32(h23);
            PL[j][0] = bc32(l01); PL[j][1] = bc32(l23);
        }

        // ---- PV(kt) from stage kt&3
        const uint32_t st = sb + AOFF_ST + (uint32_t)(kt & 3) * STAGE_B;
#pragma unroll
        for (int t = 0; t < 4; t++) {
            uint32_t ah[4] = { PH[2*t][0], PH[2*t][1], PH[2*t+1][0], PH[2*t+1][1] };
            uint32_t al[4] = { PL[2*t][0], PL[2*t][1], PL[2*t+1][0], PL[2*t+1][1] };
#pragma unroll
            for (int jp = 0; jp < 4; jp++) {
                uint32_t th[4], tl[4];
                const uint32_t vo = (uint32_t)(t * 16 * DPADB) + voff + jp * 32;
                ldm_x4t(th, st + AOFF_VH + vo);
                ldm_x4t(tl, st + AOFF_VL + vo);
                mma16816(O[jp*2],   ah, th);
                mma16816(O[jp*2],   ah, tl);
                mma16816(O[jp*2],   al, th);
                mma16816(O[jp*2+1], ah, th + 2);
                mma16816(O[jp*2+1], ah, tl + 2);
                mma16816(O[jp*2+1], al, th + 2);
            }
        }

        if (kt + 3 < 32) issue_kv(kt + 3);
        CP_COMMIT();
    }

    // ---- epilogue
    l0 += __shfl_xor_sync(0xFFFFFFFFu, l0, 1);
    l0 += __shfl_xor_sync(0xFFFFFFFFu, l0, 2);
    l1 += __shfl_xor_sync(0xFFFFFFFFu, l1, 1);
    l1 += __shfl_xor_sync(0xFFFFFFFFu, l1, 2);
    const float i0 = 1.f / l0, i1 = 1.f / l1;

    const size_t r0 = (size_t)(b * SS + qrow);
    const size_t r1 = r0 + 8;
    const int colb = h * 64 + tq2;
#pragma unroll
    for (int j = 0; j < 8; j++) {
        const int col = colb + j * 8;
        const float v0 = O[j][0] * i0, v1 = O[j][1] * i0;
        const float v2 = O[j][2] * i1, v3 = O[j][3] * i1;
        __nv_bfloat162 h01 = __float22bfloat162_rn(make_float2(v0, v1));
        float2 hf01 = __bfloat1622float2(h01);
        __nv_bfloat162 l01 = __float22bfloat162_rn(make_float2(v0 - hf01.x, v1 - hf01.y));
        __nv_bfloat162 h23 = __float22bfloat162_rn(make_float2(v2, v3));
        float2 hf23 = __bfloat1622float2(h23);
        __nv_bfloat162 l23 = __float22bfloat162_rn(make_float2(v2 - hf23.x, v3 - hf23.y));
        *(__nv_bfloat162*)(Ch + r0 * DD + col) = h01;
        *(__nv_bfloat162*)(Cl + r0 * DD + col) = l01;
        *(__nv_bfloat162*)(Ch + r1 * DD + col) = h23;
        *(__nv_bfloat162*)(Cl + r1 * DD + col) = l23;
    }
}

// ---------------------------------------------------------------------------
// Launch
// ---------------------------------------------------------------------------
extern "C" void kernel_launch(void* const* d_in, const int* in_sizes, int n_in,
                              void* d_out, int out_size)
{
    const float* query = (const float*)d_in[0];
    const int*   mask  = (const int*)d_in[1];
    const float* Wq = (const float*)d_in[2];
    const float* bq = (const float*)d_in[3];
    const float* Wk = (const float*)d_in[4];
    const float* bk = (const float*)d_in[5];
    const float* Wv = (const float*)d_in[6];
    const float* bv = (const float*)d_in[7];
    const float* Wo = (const float*)d_in[8];
    const float* bo = (const float*)d_in[9];
    float* out = (float*)d_out;

    __nv_bfloat16 *xh, *xl, *wh, *wl, *qh, *ql, *kh, *kl, *vh, *vl, *ch, *cl;
    cudaGetSymbolAddress((void**)&xh, g_xh);
    cudaGetSymbolAddress((void**)&xl, g_xl);
    cudaGetSymbolAddress((void**)&wh, g_wh);
    cudaGetSymbolAddress((void**)&wl, g_wl);
    cudaGetSymbolAddress((void**)&qh, g_qh);
    cudaGetSymbolAddress((void**)&ql, g_ql);
    cudaGetSymbolAddress((void**)&kh, g_kh);
    cudaGetSymbolAddress((void**)&kl, g_kl);
    cudaGetSymbolAddress((void**)&vh, g_vh);
    cudaGetSymbolAddress((void**)&vl, g_vl);
    cudaGetSymbolAddress((void**)&ch, g_ch);
    cudaGetSymbolAddress((void**)&cl, g_cl);

    cudaFuncSetAttribute(gemm_qkv_kernel,
                         cudaFuncAttributeMaxDynamicSharedMemorySize, SMEM_GG);
    cudaFuncSetAttribute(gemm_out_kernel,
                         cudaFuncAttributeMaxDynamicSharedMemorySize, SMEM_GG);
    cudaFuncSetAttribute(attn_mma_kernel,
                         cudaFuncAttributeMaxDynamicSharedMemorySize, SMEM_ATT);

    const int nX4 = MTOT * DD / 4;
    const int nW4 = DD * DD / 4;

    split_kernel<<<(nX4 + 255) / 256, 256>>>(query, xh, xl, nX4);
    split_kernel<<<(nW4 + 255) / 256, 256>>>(Wq, wh, wl, nW4);
    split_kernel<<<(nW4 + 255) / 256, 256>>>(Wk, wh + (size_t)DD * DD,
                                             wl + (size_t)DD * DD, nW4);
    split_kernel<<<(nW4 + 255) / 256, 256>>>(Wv, wh + 2 * (size_t)DD * DD,
                                             wl + 2 * (size_t)DD * DD, nW4);

    dim3 qkvG(DD / 128, MTOT / 128, 3);     // (8, 32, 3)
    gemm_qkv_kernel<<<qkvG, 256, SMEM_GG>>>(xh, xl, wh, wl, bq, bk, bv,
                                            qh, ql, kh, kl, vh, vl);

    dim3 aG(SS / 128, BB * HH);             // (16, 32)
    attn_mma_kernel<<<aG, 256, SMEM_ATT>>>(qh, ql, kh, kl, vh, vl, mask, ch, cl);

    split_kernel<<<(nW4 + 255) / 256, 256>>>(Wo, wh, wl, nW4);
    dim3 oG(DD / 128, MTOT / 128);          // (8, 32)
    gemm_out_kernel<<<oG, 256, SMEM_GG>>>(ch, cl, wh, wl, bo, out);
}